// round 11
// baseline (speedup 1.0000x reference)
#include <cuda_runtime.h>
#include <cuda_fp16.h>
#include <math.h>
#include <stdint.h>

// Problem constants
#define NTOK 2048
#define CDIM 768
#define EDIM 8
#define HDIM 3072
#define CAP  2048

// ---------------- scratch (static device memory; no allocations) ----------------
__device__ __half g_xbuf[(size_t)EDIM * CAP * CDIM];   // gathered activations (fp16)
__device__ __half g_u   [(size_t)EDIM * CAP * HDIM];   // h*silu(g) (fp16)
__device__ float  g_o   [(size_t)EDIM * CAP * CDIM];   // proj out split 0
__device__ float  g_o2  [(size_t)EDIM * CAP * CDIM];   // proj out split 1
__device__ float  g_o3  [(size_t)EDIM * CAP * CDIM];   // proj out split 2
__device__ __half g_wfcH[(size_t)EDIM * CDIM * HDIM];  // fp16 weights
__device__ __half g_wgtH[(size_t)EDIM * CDIM * HDIM];
__device__ __half g_wprH[(size_t)EDIM * HDIM * CDIM];
__device__ int    g_cnt [EDIM];
__device__ float  g_prob[EDIM * CAP];
__device__ int    g_pidx[2 * NTOK];

// ---------------- helpers ----------------
__device__ __forceinline__ void mma_f16(float c[4], const unsigned a[4], const unsigned b[2]) {
    asm volatile(
        "mma.sync.aligned.m16n8k16.row.col.f32.f16.f16.f32 "
        "{%0,%1,%2,%3},{%4,%5,%6,%7},{%8,%9},{%0,%1,%2,%3};\n"
        : "+f"(c[0]), "+f"(c[1]), "+f"(c[2]), "+f"(c[3])
        : "r"(a[0]), "r"(a[1]), "r"(a[2]), "r"(a[3]), "r"(b[0]), "r"(b[1]));
}

__device__ __forceinline__ void ldsm_x4(unsigned r[4], uint32_t addr) {
    asm volatile("ldmatrix.sync.aligned.m8n8.x4.shared.b16 {%0,%1,%2,%3}, [%4];"
                 : "=r"(r[0]), "=r"(r[1]), "=r"(r[2]), "=r"(r[3]) : "r"(addr));
}
__device__ __forceinline__ void ldsm_x4t(unsigned r[4], uint32_t addr) {
    asm volatile("ldmatrix.sync.aligned.m8n8.x4.trans.shared.b16 {%0,%1,%2,%3}, [%4];"
                 : "=r"(r[0]), "=r"(r[1]), "=r"(r[2]), "=r"(r[3]) : "r"(addr));
}

__device__ __forceinline__ void cpa16(uint32_t dst, const void* src, int sz) {
    asm volatile("cp.async.cg.shared.global [%0], [%1], 16, %2;"
                 :: "r"(dst), "l"(src), "r"(sz));
}
__device__ __forceinline__ void cpa16u(uint32_t dst, const void* src) {
    asm volatile("cp.async.cg.shared.global [%0], [%1], 16;"
                 :: "r"(dst), "l"(src));
}
__device__ __forceinline__ void cpa_commit() { asm volatile("cp.async.commit_group;"); }
__device__ __forceinline__ void cpa_wait1()  { asm volatile("cp.async.wait_group 1;" ::: "memory"); }
__device__ __forceinline__ void cpa_wait0()  { asm volatile("cp.async.wait_group 0;" ::: "memory"); }

__device__ __forceinline__ uint32_t smem_u32(const void* p) {
    return (uint32_t)__cvta_generic_to_shared(p);
}

// ---------------- kernel 0: init counters ----------------
__global__ void init_kernel() {
    if (threadIdx.x < EDIM) g_cnt[threadIdx.x] = 0;
}

// ---------------- weight convert: all three tensors in one launch ----------------
#define WQUARTS (EDIM * CDIM * HDIM / 4)       // float4 count per tensor: 4,718,592
#define CBLKS_PER (WQUARTS / 256)              // 18432 blocks per tensor

__global__ __launch_bounds__(256) void convert_all_kernel(const float4* __restrict__ wfc,
                                                          const float4* __restrict__ wgt,
                                                          const float4* __restrict__ wpr,
                                                          __half2* __restrict__ ofc,
                                                          __half2* __restrict__ ogt,
                                                          __half2* __restrict__ opr) {
    const int which = blockIdx.x / CBLKS_PER;
    const size_t i = (size_t)(blockIdx.x % CBLKS_PER) * 256 + threadIdx.x;
    const float4* src = (which == 0) ? wfc : (which == 1) ? wgt : wpr;
    __half2* dst = (which == 0) ? ofc : (which == 1) ? ogt : opr;
    float4 v = src[i];
    dst[2 * i + 0] = __floats2half2_rn(v.x, v.y);
    dst[2 * i + 1] = __floats2half2_rn(v.z, v.w);
}

// ---------------- kernel 1: router + dispatch/gather (fp16 gather) ----------------
__global__ __launch_bounds__(256) void router_kernel(const float* __restrict__ x,
                                                     const float* __restrict__ wr) {
    const int t = blockIdx.x * 8 + (threadIdx.x >> 5);
    if (t >= NTOK) return;
    const int lane = threadIdx.x & 31;
    const float* xr = x + (size_t)t * CDIM;

    float acc[EDIM];
#pragma unroll
    for (int e = 0; e < EDIM; e++) acc[e] = 0.f;
#pragma unroll
    for (int j = 0; j < CDIM / 32; j++) {
        int i = lane + 32 * j;
        float xv = xr[i];
        const float4* w4 = reinterpret_cast<const float4*>(wr + (size_t)i * EDIM);
        float4 w0 = w4[0], w1 = w4[1];
        acc[0] += xv * w0.x; acc[1] += xv * w0.y; acc[2] += xv * w0.z; acc[3] += xv * w0.w;
        acc[4] += xv * w1.x; acc[5] += xv * w1.y; acc[6] += xv * w1.z; acc[7] += xv * w1.w;
    }
#pragma unroll
    for (int off = 16; off > 0; off >>= 1) {
#pragma unroll
        for (int e = 0; e < EDIM; e++) acc[e] += __shfl_xor_sync(0xffffffffu, acc[e], off);
    }
    int e0 = 0; float l0 = acc[0];
#pragma unroll
    for (int e = 1; e < EDIM; e++) if (acc[e] > l0) { l0 = acc[e]; e0 = e; }
    int e1 = -1; float l1 = -INFINITY;
#pragma unroll
    for (int e = 0; e < EDIM; e++) if (e != e0 && acc[e] > l1) { l1 = acc[e]; e1 = e; }

    float ex = expf(l1 - l0);
    float p0 = 1.f / (1.f + ex);
    float p1 = ex * p0;

    int s0 = 0, s1 = 0;
    if (lane == 0) {
        s0 = atomicAdd(&g_cnt[e0], 1);
        s1 = atomicAdd(&g_cnt[e1], 1);
        g_prob[e0 * CAP + s0] = p0;
        g_prob[e1 * CAP + s1] = p1;
        g_pidx[2 * t + 0] = e0 * CAP + s0;
        g_pidx[2 * t + 1] = e1 * CAP + s1;
    }
    s0 = __shfl_sync(0xffffffffu, s0, 0);
    s1 = __shfl_sync(0xffffffffu, s1, 0);

    __half2* d0 = reinterpret_cast<__half2*>(g_xbuf + ((size_t)e0 * CAP + s0) * CDIM);
    __half2* d1 = reinterpret_cast<__half2*>(g_xbuf + ((size_t)e1 * CAP + s1) * CDIM);
    const float2* x2 = reinterpret_cast<const float2*>(xr);
#pragma unroll
    for (int j = 0; j < CDIM / 64; j++) {
        int i = lane + 32 * j;
        float2 v = x2[i];
        __half2 h = __floats2half2_rn(v.x, v.y);
        d0[i] = h;
        d1[i] = h;
    }
}

// ======== GEMM1: fused fc+gate, block 128x64(x2), BK=64, 8 warps (4x2), warp 32x32x2mat ========
// 3-stage ring, chunk-interleaved cp.async. Stage: A 128x72 | Bf 64x72 | Bg 64x72 = 18432 halves
#define G1_AH    9216
#define G1_BH    4608
#define G1_STG   (G1_AH + 2 * G1_BH)
#define G1_SMEM_BYTES (3 * G1_STG * 2)   // 110592

__global__ __launch_bounds__(256, 2) void gemm1_kernel(const float* __restrict__ bfc,
                                                       const float* __restrict__ bgt) {
    extern __shared__ __half smh[];
    const int e   = blockIdx.z;
    const int cnt = g_cnt[e];
    const int m0  = blockIdx.y * 128;
    if (m0 >= cnt) return;
    const int n0  = blockIdx.x * 64;

    const __half* Ag = g_xbuf + (size_t)e * CAP * CDIM;
    const __half* B0 = g_wfcH + (size_t)e * CDIM * HDIM;
    const __half* B1 = g_wgtH + (size_t)e * CDIM * HDIM;

    const int tid = threadIdx.x, lane = tid & 31, wid = tid >> 5;
    const int wm = (wid & 3) * 32, wn = (wid >> 2) * 32;
    const int gq = lane >> 2, tg = lane & 3;
    const int grp = lane >> 3, rin = lane & 7;

    const uint32_t sBase = smem_u32(smh);

    // chunk c (0..3): one A cpa + one B cpa per thread; commit on c==3
    auto load_chunk = [&](int buf, int k0, int c) {
        const uint32_t sA  = sBase + (uint32_t)(buf * G1_STG) * 2;
        const uint32_t sBf = sA + G1_AH * 2;
        const uint32_t sBg = sBf + G1_BH * 2;
        {
            int v = tid + 256 * c, row = v >> 3, c16 = v & 7;
            int sz = (m0 + row < cnt) ? 16 : 0;
            cpa16(sA + (uint32_t)(row * 72 + c16 * 8) * 2,
                  Ag + (size_t)(m0 + row) * CDIM + k0 + c16 * 8, sz);
        }
        {
            int i = c >> 1;
            int v = tid + 256 * i, row = v >> 3, c16 = v & 7;
            size_t off = (size_t)(k0 + row) * HDIM + n0 + c16 * 8;
            uint32_t so = (uint32_t)(row * 72 + c16 * 8) * 2;
            if ((c & 1) == 0) cpa16u(sBf + so, B0 + off);
            else              cpa16u(sBg + so, B1 + off);
        }
        if (c == 3) cpa_commit();
    };

    float cf[2][4][4] = {};
    float cg[2][4][4] = {};

    const int NIT = CDIM / 64;  // 12
#pragma unroll
    for (int c = 0; c < 4; c++) load_chunk(0, 0, c);
#pragma unroll
    for (int c = 0; c < 4; c++) load_chunk(1, 64, c);

#pragma unroll 1
    for (int it = 0; it < NIT; ++it) {
        if (it + 1 < NIT) cpa_wait1(); else cpa_wait0();
        __syncthreads();
        // buffer (it+2)%3 == (it-1)%3 was consumed last iter; safe after this barrier

        const int cur = it % 3;
        const int nbuf = (it + 2) % 3;
        const bool more = (it + 2 < NIT);
        const int k2 = (it + 2) * 64;

        const uint32_t aB  = sBase + (uint32_t)(cur * G1_STG) * 2;
        const uint32_t bfB = aB + G1_AH * 2;
        const uint32_t bgB = bfB + G1_BH * 2;

        unsigned uA[2][2][4], uBf[2][4][2], uBg[2][4][2];

        auto ldfrag = [&](int ks, int s) {
            const int kb = ks * 16;
#pragma unroll
            for (int mt = 0; mt < 2; mt++) {
                int r = wm + mt * 16 + (grp & 1) * 8 + rin;
                ldsm_x4(uA[s][mt], aB + (uint32_t)((r * 72 + kb + (grp >> 1) * 8) * 2));
            }
            {
                int kr = kb + (grp & 1) * 8 + rin;
#pragma unroll
                for (int p = 0; p < 2; p++) {
                    int cc = wn + p * 16 + (grp >> 1) * 8;
                    unsigned r4[4];
                    ldsm_x4t(r4, bfB + (uint32_t)((kr * 72 + cc) * 2));
                    uBf[s][2 * p + 0][0] = r4[0]; uBf[s][2 * p + 0][1] = r4[1];
                    uBf[s][2 * p + 1][0] = r4[2]; uBf[s][2 * p + 1][1] = r4[3];
                    ldsm_x4t(r4, bgB + (uint32_t)((kr * 72 + cc) * 2));
                    uBg[s][2 * p + 0][0] = r4[0]; uBg[s][2 * p + 0][1] = r4[1];
                    uBg[s][2 * p + 1][0] = r4[2]; uBg[s][2 * p + 1][1] = r4[3];
                }
            }
        };

        ldfrag(0, 0);
#pragma unroll
        for (int ks = 0; ks < 4; ks++) {
            const int s = ks & 1;
            if (ks < 3) ldfrag(ks + 1, s ^ 1);
            if (more) load_chunk(nbuf, k2, ks);   // spread STS across MMA phases
#pragma unroll
            for (int mt = 0; mt < 2; mt++)
#pragma unroll
                for (int nt = 0; nt < 4; nt++) {
                    mma_f16(cf[mt][nt], uA[s][mt], uBf[s][nt]);
                    mma_f16(cg[mt][nt], uA[s][mt], uBg[s][nt]);
                }
        }
    }

    // epilogue: u = (h+bfc) * silu(g+bg) -> fp16
    __half* U = g_u + (size_t)e * CAP * HDIM;
#pragma unroll
    for (int mt = 0; mt < 2; mt++) {
#pragma unroll
        for (int nt = 0; nt < 4; nt++) {
            int col = n0 + wn + nt * 8 + tg * 2;
            float bf0 = bfc[(size_t)e * HDIM + col], bf1 = bfc[(size_t)e * HDIM + col + 1];
            float bg0 = bgt[(size_t)e * HDIM + col], bg1 = bgt[(size_t)e * HDIM + col + 1];
            int r0 = m0 + wm + mt * 16 + gq;
            if (r0 < cnt) {
                float h0 = cf[mt][nt][0] + bf0, h1 = cf[mt][nt][1] + bf1;
                float q0 = cg[mt][nt][0] + bg0, q1 = cg[mt][nt][1] + bg1;
                float u0 = h0 * (q0 / (1.f + expf(-q0)));
                float u1 = h1 * (q1 / (1.f + expf(-q1)));
                *reinterpret_cast<__half2*>(U + (size_t)r0 * HDIM + col) = __floats2half2_rn(u0, u1);
            }
            int r1 = r0 + 8;
            if (r1 < cnt) {
                float h0 = cf[mt][nt][2] + bf0, h1 = cf[mt][nt][3] + bf1;
                float q0 = cg[mt][nt][2] + bg0, q1 = cg[mt][nt][3] + bg1;
                float u0 = h0 * (q0 / (1.f + expf(-q0)));
                float u1 = h1 * (q1 / (1.f + expf(-q1)));
                *reinterpret_cast<__half2*>(U + (size_t)r1 * HDIM + col) = __floats2half2_rn(u0, u1);
            }
        }
    }
}

// ======== GEMM2: proj, block 128x128, 8 warps (2x4), warp 64x32, BK=64, split-K=3 ========
// 3-stage ring, chunk-interleaved. Stage: A 128x72 | B 64x136 = 17920 halves
#define G2_AH   9216
#define G2_BH   8704
#define G2_STG  (G2_AH + G2_BH)
#define G2_SMEM_BYTES (3 * G2_STG * 2)   // 107520
#define NSPLIT 3
#define SPLITK (HDIM / NSPLIT)   // 1024

__global__ __launch_bounds__(256, 2) void gemm2_kernel(const float* __restrict__ bpr) {
    extern __shared__ __half smh[];
    const int e     = blockIdx.z / NSPLIT;
    const int split = blockIdx.z % NSPLIT;
    const int cnt   = g_cnt[e];
    const int m0    = blockIdx.y * 128;
    if (m0 >= cnt) return;
    const int n0    = blockIdx.x * 128;
    const int kbase = split * SPLITK;

    const __half* Ag = g_u + (size_t)e * CAP * HDIM + kbase;
    const __half* Bp = g_wprH + (size_t)e * HDIM * CDIM + (size_t)kbase * CDIM;

    const int tid = threadIdx.x, lane = tid & 31, wid = tid >> 5;
    const int wm = (wid & 1) * 64, wn = (wid >> 1) * 32;
    const int gq = lane >> 2, tg = lane & 3;
    const int grp = lane >> 3, rin = lane & 7;

    const uint32_t sBase = smem_u32(smh);

    auto load_chunk = [&](int buf, int k0, int c) {
        const uint32_t sA = sBase + (uint32_t)(buf * G2_STG) * 2;
        const uint32_t sB = sA + G2_AH * 2;
        {
            int v = tid + 256 * c, row = v >> 3, c16 = v & 7;
            int sz = (m0 + row < cnt) ? 16 : 0;
            cpa16(sA + (uint32_t)(row * 72 + c16 * 8) * 2,
                  Ag + (size_t)(m0 + row) * HDIM + k0 + c16 * 8, sz);
        }
        {
            int v = tid + 256 * c, row = v >> 4, c16 = v & 15;
            cpa16u(sB + (uint32_t)(row * 136 + c16 * 8) * 2,
                   Bp + (size_t)(k0 + row) * CDIM + n0 + c16 * 8);
        }
        if (c == 3) cpa_commit();
    };

    float acc[4][4][4] = {};

    const int NIT = SPLITK / 64;  // 16
#pragma unroll
    for (int c = 0; c < 4; c++) load_chunk(0, 0, c);
#pragma unroll
    for (int c = 0; c < 4; c++) load_chunk(1, 64, c);

#pragma unroll 1
    for (int it = 0; it < NIT; ++it) {
        if (it + 1 < NIT) cpa_wait1(); else cpa_wait0();
        __syncthreads();

        const int cur = it % 3;
        const int nbuf = (it + 2) % 3;
        const bool more = (it + 2 < NIT);
        const int k2 = (it + 2) * 64;

        const uint32_t aB = sBase + (uint32_t)(cur * G2_STG) * 2;
        const uint32_t bB = aB + G2_AH * 2;

        unsigned uA[2][4][4], uB[2][4][2];

        auto ldfrag = [&](int ks, int s) {
            const int kb = ks * 16;
#pragma unroll
            for (int mt = 0; mt < 4; mt++) {
                int r = wm + mt * 16 + (grp & 1) * 8 + rin;
                ldsm_x4(uA[s][mt], aB + (uint32_t)((r * 72 + kb + (grp >> 1) * 8) * 2));
            }
            {
                int kr = kb + (grp & 1) * 8 + rin;
#pragma unroll
                for (int p = 0; p < 2; p++) {
                    int cc = wn + p * 16 + (grp >> 1) * 8;
                    unsigned r4[4];
                    ldsm_x4t(r4, bB + (uint32_t)((kr * 136 + cc) * 2));
                    uB[s][2 * p + 0][0] = r4[0]; uB[s][2 * p + 0][1] = r4[1];
                    uB[s][2 * p + 1][0] = r4[2]; uB[s][2 * p + 1][1] = r4[3];
                }
            }
        };

        ldfrag(0, 0);
#pragma unroll
        for (int ks = 0; ks < 4; ks++) {
            const int s = ks & 1;
            if (ks < 3) ldfrag(ks + 1, s ^ 1);
            if (more) load_chunk(nbuf, k2, ks);
#pragma unroll
            for (int mt = 0; mt < 4; mt++)
#pragma unroll
                for (int nt = 0; nt < 4; nt++)
                    mma_f16(acc[mt][nt], uA[s][mt], uB[s][nt]);
        }
    }

    float* O = (split == 0 ? g_o : (split == 1 ? g_o2 : g_o3)) + (size_t)e * CAP * CDIM;
#pragma unroll
    for (int mt = 0; mt < 4; mt++) {
#pragma unroll
        for (int nt = 0; nt < 4; nt++) {
            int col = n0 + wn + nt * 8 + tg * 2;
            float b0 = 0.f, b1 = 0.f;
            if (split == 0) {
                b0 = bpr[(size_t)e * CDIM + col];
                b1 = bpr[(size_t)e * CDIM + col + 1];
            }
            int r0 = m0 + wm + mt * 16 + gq;
            if (r0 < cnt) {
                float2 o; o.x = acc[mt][nt][0] + b0; o.y = acc[mt][nt][1] + b1;
                *(float2*)(O + (size_t)r0 * CDIM + col) = o;
            }
            int r1 = r0 + 8;
            if (r1 < cnt) {
                float2 o; o.x = acc[mt][nt][2] + b0; o.y = acc[mt][nt][3] + b1;
                *(float2*)(O + (size_t)r1 * CDIM + col) = o;
            }
        }
    }
}

// ---------------- kernel 4: deterministic combine (sums 3 split-K parts) ----------------
__global__ __launch_bounds__(192) void combine_kernel(float* __restrict__ out) {
    const int t = blockIdx.x;
    const int c4 = threadIdx.x;
    const int i0 = g_pidx[2 * t + 0];
    const int i1 = g_pidx[2 * t + 1];
    const float p0 = g_prob[i0];
    const float p1 = g_prob[i1];
    const float4 a0 = reinterpret_cast<const float4*>(g_o  + (size_t)i0 * CDIM)[c4];
    const float4 a1 = reinterpret_cast<const float4*>(g_o2 + (size_t)i0 * CDIM)[c4];
    const float4 a2 = reinterpret_cast<const float4*>(g_o3 + (size_t)i0 * CDIM)[c4];
    const float4 b0 = reinterpret_cast<const float4*>(g_o  + (size_t)i1 * CDIM)[c4];
    const float4 b1 = reinterpret_cast<const float4*>(g_o2 + (size_t)i1 * CDIM)[c4];
    const float4 b2 = reinterpret_cast<const float4*>(g_o3 + (size_t)i1 * CDIM)[c4];
    float4 y;
    y.x = p0 * (a0.x + a1.x + a2.x) + p1 * (b0.x + b1.x + b2.x);
    y.y = p0 * (a0.y + a1.y + a2.y) + p1 * (b0.y + b1.y + b2.y);
    y.z = p0 * (a0.z + a1.z + a2.z) + p1 * (b0.z + b1.z + b2.z);
    y.w = p0 * (a0.w + a1.w + a2.w) + p1 * (b0.w + b1.w + b2.w);
    reinterpret_cast<float4*>(out + (size_t)t * CDIM)[c4] = y;
}

// ---------------- launch ----------------
extern "C" void kernel_launch(void* const* d_in, const int* in_sizes, int n_in,
                              void* d_out, int out_size) {
    const float* x    = (const float*)d_in[0];
    const float* wr   = (const float*)d_in[1];
    const float* wfc  = (const float*)d_in[2];
    const float* bfc  = (const float*)d_in[3];
    const float* wgt  = (const float*)d_in[4];
    const float* bgt  = (const float*)d_in[5];
    const float* wpr  = (const float*)d_in[6];
    const float* bpr  = (const float*)d_in[7];
    float* out = (float*)d_out;

    // REQUIRED: dynamic smem exceeds the 48KB default opt-in
    cudaFuncSetAttribute(gemm1_kernel, cudaFuncAttributeMaxDynamicSharedMemorySize, G1_SMEM_BYTES);
    cudaFuncSetAttribute(gemm2_kernel, cudaFuncAttributeMaxDynamicSharedMemorySize, G2_SMEM_BYTES);

    __half* wfcH; cudaGetSymbolAddress((void**)&wfcH, g_wfcH);
    __half* wgtH; cudaGetSymbolAddress((void**)&wgtH, g_wgtH);
    __half* wprH; cudaGetSymbolAddress((void**)&wprH, g_wprH);

    init_kernel<<<1, 32>>>();
    convert_all_kernel<<<3 * CBLKS_PER, 256>>>((const float4*)wfc, (const float4*)wgt,
                                               (const float4*)wpr,
                                               (__half2*)wfcH, (__half2*)wgtH, (__half2*)wprH);
    router_kernel<<<NTOK / 8, 256>>>(x, wr);
    gemm1_kernel<<<dim3(HDIM / 64, CAP / 128, EDIM), 256, G1_SMEM_BYTES>>>(bfc, bgt);
    gemm2_kernel<<<dim3(CDIM / 128, CAP / 128, EDIM * NSPLIT), 256, G2_SMEM_BYTES>>>(bpr);
    combine_kernel<<<NTOK, 192>>>(out);
}

// round 12
// speedup vs baseline: 1.1957x; 1.1957x over previous
#include <cuda_runtime.h>
#include <cuda_fp16.h>
#include <math.h>
#include <stdint.h>

// Problem constants
#define NTOK 2048
#define CDIM 768
#define EDIM 8
#define HDIM 3072
#define CAP  2048

// ---------------- scratch (static device memory; no allocations) ----------------
__device__ __half g_xbuf[(size_t)EDIM * CAP * CDIM];   // gathered activations (fp16)
__device__ __half g_u   [(size_t)EDIM * CAP * HDIM];   // h*silu(g) (fp16)
__device__ float  g_o   [(size_t)EDIM * CAP * CDIM];   // proj out split 0
__device__ float  g_o2  [(size_t)EDIM * CAP * CDIM];   // proj out split 1
__device__ float  g_o3  [(size_t)EDIM * CAP * CDIM];   // proj out split 2
__device__ __half g_wfcH[(size_t)EDIM * CDIM * HDIM];  // fp16 weights
__device__ __half g_wgtH[(size_t)EDIM * CDIM * HDIM];
__device__ __half g_wprH[(size_t)EDIM * HDIM * CDIM];
__device__ int    g_cnt [EDIM];
__device__ float  g_prob[EDIM * CAP];
__device__ int    g_pidx[2 * NTOK];

// ---------------- helpers ----------------
__device__ __forceinline__ void mma_f16(float c[4], const unsigned a[4], const unsigned b[2]) {
    asm volatile(
        "mma.sync.aligned.m16n8k16.row.col.f32.f16.f16.f32 "
        "{%0,%1,%2,%3},{%4,%5,%6,%7},{%8,%9},{%0,%1,%2,%3};\n"
        : "+f"(c[0]), "+f"(c[1]), "+f"(c[2]), "+f"(c[3])
        : "r"(a[0]), "r"(a[1]), "r"(a[2]), "r"(a[3]), "r"(b[0]), "r"(b[1]));
}

__device__ __forceinline__ void ldsm_x4(unsigned r[4], uint32_t addr) {
    asm volatile("ldmatrix.sync.aligned.m8n8.x4.shared.b16 {%0,%1,%2,%3}, [%4];"
                 : "=r"(r[0]), "=r"(r[1]), "=r"(r[2]), "=r"(r[3]) : "r"(addr));
}
__device__ __forceinline__ void ldsm_x4t(unsigned r[4], uint32_t addr) {
    asm volatile("ldmatrix.sync.aligned.m8n8.x4.trans.shared.b16 {%0,%1,%2,%3}, [%4];"
                 : "=r"(r[0]), "=r"(r[1]), "=r"(r[2]), "=r"(r[3]) : "r"(addr));
}

__device__ __forceinline__ void cpa16(uint32_t dst, const void* src, int sz) {
    asm volatile("cp.async.cg.shared.global [%0], [%1], 16, %2;"
                 :: "r"(dst), "l"(src), "r"(sz));
}
__device__ __forceinline__ void cpa16u(uint32_t dst, const void* src) {
    asm volatile("cp.async.cg.shared.global [%0], [%1], 16;"
                 :: "r"(dst), "l"(src));
}
__device__ __forceinline__ void cpa_commit() { asm volatile("cp.async.commit_group;"); }
__device__ __forceinline__ void cpa_wait1()  { asm volatile("cp.async.wait_group 1;" ::: "memory"); }
__device__ __forceinline__ void cpa_wait0()  { asm volatile("cp.async.wait_group 0;" ::: "memory"); }

__device__ __forceinline__ uint32_t smem_u32(const void* p) {
    return (uint32_t)__cvta_generic_to_shared(p);
}

// ---------------- kernel 0: init counters ----------------
__global__ void init_kernel() {
    if (threadIdx.x < EDIM) g_cnt[threadIdx.x] = 0;
}

// ---------------- fused pre-pass: router blocks [0,256) + weight-convert blocks ----------------
// Router and convert are fully independent (router: x -> g_xbuf/g_cnt/g_prob/g_pidx;
// convert: w* -> g_w*H). Convert is DRAM-bound with idle SMs, so router hides under it.
#define WQUARTS (EDIM * CDIM * HDIM / 4)       // float4 per tensor: 4,718,592
#define CBLKS_PER (WQUARTS / 256)              // 18432 blocks per tensor
#define RBLKS (NTOK / 8)                       // 256 router blocks

__global__ __launch_bounds__(256) void prepass_kernel(const float* __restrict__ x,
                                                      const float* __restrict__ wr,
                                                      const float4* __restrict__ wfc,
                                                      const float4* __restrict__ wgt,
                                                      const float4* __restrict__ wpr,
                                                      __half2* __restrict__ ofc,
                                                      __half2* __restrict__ ogt,
                                                      __half2* __restrict__ opr) {
    if (blockIdx.x >= RBLKS) {
        // ---- convert portion ----
        const int cb = blockIdx.x - RBLKS;
        const int which = cb / CBLKS_PER;
        const size_t i = (size_t)(cb % CBLKS_PER) * 256 + threadIdx.x;
        const float4* src = (which == 0) ? wfc : (which == 1) ? wgt : wpr;
        __half2* dst = (which == 0) ? ofc : (which == 1) ? ogt : opr;
        float4 v = src[i];
        dst[2 * i + 0] = __floats2half2_rn(v.x, v.y);
        dst[2 * i + 1] = __floats2half2_rn(v.z, v.w);
        return;
    }

    // ---- router portion ----
    const int t = blockIdx.x * 8 + (threadIdx.x >> 5);
    const int lane = threadIdx.x & 31;
    const float* xr = x + (size_t)t * CDIM;

    float acc[EDIM];
#pragma unroll
    for (int e = 0; e < EDIM; e++) acc[e] = 0.f;
#pragma unroll
    for (int j = 0; j < CDIM / 32; j++) {
        int i = lane + 32 * j;
        float xv = xr[i];
        const float4* w4 = reinterpret_cast<const float4*>(wr + (size_t)i * EDIM);
        float4 w0 = w4[0], w1 = w4[1];
        acc[0] += xv * w0.x; acc[1] += xv * w0.y; acc[2] += xv * w0.z; acc[3] += xv * w0.w;
        acc[4] += xv * w1.x; acc[5] += xv * w1.y; acc[6] += xv * w1.z; acc[7] += xv * w1.w;
    }
#pragma unroll
    for (int off = 16; off > 0; off >>= 1) {
#pragma unroll
        for (int e = 0; e < EDIM; e++) acc[e] += __shfl_xor_sync(0xffffffffu, acc[e], off);
    }
    int e0 = 0; float l0 = acc[0];
#pragma unroll
    for (int e = 1; e < EDIM; e++) if (acc[e] > l0) { l0 = acc[e]; e0 = e; }
    int e1 = -1; float l1 = -INFINITY;
#pragma unroll
    for (int e = 0; e < EDIM; e++) if (e != e0 && acc[e] > l1) { l1 = acc[e]; e1 = e; }

    float ex = expf(l1 - l0);
    float p0 = 1.f / (1.f + ex);
    float p1 = ex * p0;

    int s0 = 0, s1 = 0;
    if (lane == 0) {
        s0 = atomicAdd(&g_cnt[e0], 1);
        s1 = atomicAdd(&g_cnt[e1], 1);
        g_prob[e0 * CAP + s0] = p0;
        g_prob[e1 * CAP + s1] = p1;
        g_pidx[2 * t + 0] = e0 * CAP + s0;
        g_pidx[2 * t + 1] = e1 * CAP + s1;
    }
    s0 = __shfl_sync(0xffffffffu, s0, 0);
    s1 = __shfl_sync(0xffffffffu, s1, 0);

    __half2* d0 = reinterpret_cast<__half2*>(g_xbuf + ((size_t)e0 * CAP + s0) * CDIM);
    __half2* d1 = reinterpret_cast<__half2*>(g_xbuf + ((size_t)e1 * CAP + s1) * CDIM);
    const float2* x2 = reinterpret_cast<const float2*>(xr);
#pragma unroll
    for (int j = 0; j < CDIM / 64; j++) {
        int i = lane + 32 * j;
        float2 v = x2[i];
        __half2 h = __floats2half2_rn(v.x, v.y);
        d0[i] = h;
        d1[i] = h;
    }
}

// ======== GEMM1: fused fc+gate, block 128x64(x2), BK=64, fp16 mma, cp.async 2-stage ========
// smem halves: A[2][128*72] | Bf[2][64*72] | Bg[2][64*72]  = 36864 halves = 73728 B
#define G1_AH    9216            // halves per A stage
#define G1_BH    4608            // halves per B stage (each matrix)
#define G1_BF0H  (2 * G1_AH)
#define G1_BG0H  (G1_BF0H + 2 * G1_BH)
#define G1_SMEM_BYTES ((G1_BG0H + 2 * G1_BH) * 2)

__global__ __launch_bounds__(256, 2) void gemm1_kernel(const float* __restrict__ bfc,
                                                       const float* __restrict__ bgt) {
    extern __shared__ __half smh[];
    const int e   = blockIdx.z;
    const int cnt = g_cnt[e];
    const int m0  = blockIdx.y * 128;
    if (m0 >= cnt) return;
    const int n0  = blockIdx.x * 64;

    const __half* Ag = g_xbuf + (size_t)e * CAP * CDIM;
    const __half* B0 = g_wfcH + (size_t)e * CDIM * HDIM;
    const __half* B1 = g_wgtH + (size_t)e * CDIM * HDIM;

    const int tid = threadIdx.x, lane = tid & 31, wid = tid >> 5;
    const int wm = (wid & 3) * 32, wn = (wid >> 2) * 32;
    const int gq = lane >> 2, tg = lane & 3;
    const int grp = lane >> 3, rin = lane & 7;

    const uint32_t sBase = smem_u32(smh);

    auto load_stage = [&](int buf, int k0) {
        // A: 128 rows x 128B = 1024 chunks, 4/thread
#pragma unroll
        for (int i = 0; i < 4; i++) {
            int v = tid + 256 * i, row = v >> 3, c16 = v & 7;
            int sz = (m0 + row < cnt) ? 16 : 0;
            cpa16(sBase + (uint32_t)(buf * G1_AH + row * 72 + c16 * 8) * 2,
                  Ag + (size_t)(m0 + row) * CDIM + k0 + c16 * 8, sz);
        }
        // B each: 64 rows x 128B = 512 chunks, 2/thread per matrix
#pragma unroll
        for (int i = 0; i < 2; i++) {
            int v = tid + 256 * i, row = v >> 3, c16 = v & 7;
            size_t off = (size_t)(k0 + row) * HDIM + n0 + c16 * 8;
            cpa16u(sBase + (uint32_t)(G1_BF0H + buf * G1_BH + row * 72 + c16 * 8) * 2, B0 + off);
            cpa16u(sBase + (uint32_t)(G1_BG0H + buf * G1_BH + row * 72 + c16 * 8) * 2, B1 + off);
        }
        cpa_commit();
    };

    float cf[2][4][4] = {};
    float cg[2][4][4] = {};

    const int NIT = CDIM / 64;  // 12
    load_stage(0, 0);
    load_stage(1, 64);

#pragma unroll 1
    for (int it = 0; it < NIT; ++it) {
        const int cur = it & 1;
        if (it + 1 < NIT) cpa_wait1(); else cpa_wait0();
        __syncthreads();

        const uint32_t aB  = sBase + (uint32_t)(cur * G1_AH) * 2;
        const uint32_t bfB = sBase + (uint32_t)(G1_BF0H + cur * G1_BH) * 2;
        const uint32_t bgB = sBase + (uint32_t)(G1_BG0H + cur * G1_BH) * 2;

        unsigned uA[2][2][4], uBf[2][4][2], uBg[2][4][2];

        auto ldfrag = [&](int ks, int s) {
            const int kb = ks * 16;
#pragma unroll
            for (int mt = 0; mt < 2; mt++) {
                int r = wm + mt * 16 + (grp & 1) * 8 + rin;
                ldsm_x4(uA[s][mt], aB + (uint32_t)((r * 72 + kb + (grp >> 1) * 8) * 2));
            }
#pragma unroll
            for (int p = 0; p < 2; p++) {
                int kr = kb + (grp & 1) * 8 + rin;
                int cc = wn + p * 16 + (grp >> 1) * 8;
                unsigned r4[4];
                ldsm_x4t(r4, bfB + (uint32_t)((kr * 72 + cc) * 2));
                uBf[s][2 * p + 0][0] = r4[0]; uBf[s][2 * p + 0][1] = r4[1];
                uBf[s][2 * p + 1][0] = r4[2]; uBf[s][2 * p + 1][1] = r4[3];
                ldsm_x4t(r4, bgB + (uint32_t)((kr * 72 + cc) * 2));
                uBg[s][2 * p + 0][0] = r4[0]; uBg[s][2 * p + 0][1] = r4[1];
                uBg[s][2 * p + 1][0] = r4[2]; uBg[s][2 * p + 1][1] = r4[3];
            }
        };

        ldfrag(0, 0);
#pragma unroll
        for (int ks = 0; ks < 4; ks++) {
            const int s = ks & 1;
            if (ks < 3) ldfrag(ks + 1, s ^ 1);
#pragma unroll
            for (int mt = 0; mt < 2; mt++)
#pragma unroll
                for (int nt = 0; nt < 4; nt++) {
                    mma_f16(cf[mt][nt], uA[s][mt], uBf[s][nt]);
                    mma_f16(cg[mt][nt], uA[s][mt], uBg[s][nt]);
                }
        }
        __syncthreads();
        if (it + 2 < NIT) load_stage(cur, (it + 2) * 64);
    }

    // epilogue: u = (h+bfc) * silu(g+bg) -> fp16
    __half* U = g_u + (size_t)e * CAP * HDIM;
#pragma unroll
    for (int mt = 0; mt < 2; mt++) {
#pragma unroll
        for (int nt = 0; nt < 4; nt++) {
            int col = n0 + wn + nt * 8 + tg * 2;
            float bf0 = bfc[(size_t)e * HDIM + col], bf1 = bfc[(size_t)e * HDIM + col + 1];
            float bg0 = bgt[(size_t)e * HDIM + col], bg1 = bgt[(size_t)e * HDIM + col + 1];
            int r0 = m0 + wm + mt * 16 + gq;
            if (r0 < cnt) {
                float h0 = cf[mt][nt][0] + bf0, h1 = cf[mt][nt][1] + bf1;
                float q0 = cg[mt][nt][0] + bg0, q1 = cg[mt][nt][1] + bg1;
                float u0 = h0 * (q0 / (1.f + expf(-q0)));
                float u1 = h1 * (q1 / (1.f + expf(-q1)));
                *reinterpret_cast<__half2*>(U + (size_t)r0 * HDIM + col) = __floats2half2_rn(u0, u1);
            }
            int r1 = r0 + 8;
            if (r1 < cnt) {
                float h0 = cf[mt][nt][2] + bf0, h1 = cf[mt][nt][3] + bf1;
                float q0 = cg[mt][nt][2] + bg0, q1 = cg[mt][nt][3] + bg1;
                float u0 = h0 * (q0 / (1.f + expf(-q0)));
                float u1 = h1 * (q1 / (1.f + expf(-q1)));
                *reinterpret_cast<__half2*>(U + (size_t)r1 * HDIM + col) = __floats2half2_rn(u0, u1);
            }
        }
    }
}

// ======== GEMM2: proj, block 128x128, warp 64x32, BK=64, fp16 mma, 2-stage, split-K=3 ========
// smem halves: A[2][128*72] | B[2][64*136] = 35840 halves = 71680 B
#define G2_AH   9216
#define G2_BH   8704
#define G2_B0H  (2 * G2_AH)
#define G2_SMEM_BYTES ((G2_B0H + 2 * G2_BH) * 2)
#define NSPLIT 3
#define SPLITK (HDIM / NSPLIT)   // 1024

__global__ __launch_bounds__(256, 2) void gemm2_kernel(const float* __restrict__ bpr) {
    extern __shared__ __half smh[];
    const int e     = blockIdx.z / NSPLIT;
    const int split = blockIdx.z % NSPLIT;
    const int cnt   = g_cnt[e];
    const int m0    = blockIdx.y * 128;
    if (m0 >= cnt) return;
    const int n0    = blockIdx.x * 128;
    const int kbase = split * SPLITK;

    const __half* Ag = g_u + (size_t)e * CAP * HDIM + kbase;
    const __half* Bp = g_wprH + (size_t)e * HDIM * CDIM + (size_t)kbase * CDIM;

    const int tid = threadIdx.x, lane = tid & 31, wid = tid >> 5;
    const int wm = (wid & 1) * 64, wn = (wid >> 1) * 32;
    const int gq = lane >> 2, tg = lane & 3;
    const int grp = lane >> 3, rin = lane & 7;

    const uint32_t sBase = smem_u32(smh);

    auto load_stage = [&](int buf, int k0) {
#pragma unroll
        for (int i = 0; i < 4; i++) {
            int v = tid + 256 * i, row = v >> 3, c16 = v & 7;
            int sz = (m0 + row < cnt) ? 16 : 0;
            cpa16(sBase + (uint32_t)(buf * G2_AH + row * 72 + c16 * 8) * 2,
                  Ag + (size_t)(m0 + row) * HDIM + k0 + c16 * 8, sz);
        }
        // B: 64 rows x 256B = 1024 chunks, 4/thread
#pragma unroll
        for (int i = 0; i < 4; i++) {
            int v = tid + 256 * i, row = v >> 4, c16 = v & 15;
            cpa16u(sBase + (uint32_t)(G2_B0H + buf * G2_BH + row * 136 + c16 * 8) * 2,
                   Bp + (size_t)(k0 + row) * CDIM + n0 + c16 * 8);
        }
        cpa_commit();
    };

    float acc[4][4][4] = {};

    const int NIT = SPLITK / 64;  // 16
    load_stage(0, 0);
    load_stage(1, 64);

#pragma unroll 1
    for (int it = 0; it < NIT; ++it) {
        const int cur = it & 1;
        if (it + 1 < NIT) cpa_wait1(); else cpa_wait0();
        __syncthreads();

        const uint32_t aB = sBase + (uint32_t)(cur * G2_AH) * 2;
        const uint32_t bB = sBase + (uint32_t)(G2_B0H + cur * G2_BH) * 2;

        unsigned uA[2][4][4], uB[2][4][2];

        auto ldfrag = [&](int ks, int s) {
            const int kb = ks * 16;
#pragma unroll
            for (int mt = 0; mt < 4; mt++) {
                int r = wm + mt * 16 + (grp & 1) * 8 + rin;
                ldsm_x4(uA[s][mt], aB + (uint32_t)((r * 72 + kb + (grp >> 1) * 8) * 2));
            }
            {
                int kr = kb + (grp & 1) * 8 + rin;
#pragma unroll
                for (int p = 0; p < 2; p++) {
                    int cc = wn + p * 16 + (grp >> 1) * 8;
                    unsigned r4[4];
                    ldsm_x4t(r4, bB + (uint32_t)((kr * 136 + cc) * 2));
                    uB[s][2 * p + 0][0] = r4[0]; uB[s][2 * p + 0][1] = r4[1];
                    uB[s][2 * p + 1][0] = r4[2]; uB[s][2 * p + 1][1] = r4[3];
                }
            }
        };

        ldfrag(0, 0);
#pragma unroll
        for (int ks = 0; ks < 4; ks++) {
            const int s = ks & 1;
            if (ks < 3) ldfrag(ks + 1, s ^ 1);
#pragma unroll
            for (int mt = 0; mt < 4; mt++)
#pragma unroll
                for (int nt = 0; nt < 4; nt++)
                    mma_f16(acc[mt][nt], uA[s][mt], uB[s][nt]);
        }
        __syncthreads();
        if (it + 2 < NIT) load_stage(cur, (it + 2) * 64);
    }

    float* O = (split == 0 ? g_o : (split == 1 ? g_o2 : g_o3)) + (size_t)e * CAP * CDIM;
#pragma unroll
    for (int mt = 0; mt < 4; mt++) {
#pragma unroll
        for (int nt = 0; nt < 4; nt++) {
            int col = n0 + wn + nt * 8 + tg * 2;
            float b0 = 0.f, b1 = 0.f;
            if (split == 0) {
                b0 = bpr[(size_t)e * CDIM + col];
                b1 = bpr[(size_t)e * CDIM + col + 1];
            }
            int r0 = m0 + wm + mt * 16 + gq;
            if (r0 < cnt) {
                float2 o; o.x = acc[mt][nt][0] + b0; o.y = acc[mt][nt][1] + b1;
                *(float2*)(O + (size_t)r0 * CDIM + col) = o;
            }
            int r1 = r0 + 8;
            if (r1 < cnt) {
                float2 o; o.x = acc[mt][nt][2] + b0; o.y = acc[mt][nt][3] + b1;
                *(float2*)(O + (size_t)r1 * CDIM + col) = o;
            }
        }
    }
}

// ---------------- kernel 4: deterministic combine (sums 3 split-K parts) ----------------
__global__ __launch_bounds__(192) void combine_kernel(float* __restrict__ out) {
    const int t = blockIdx.x;
    const int c4 = threadIdx.x;
    const int i0 = g_pidx[2 * t + 0];
    const int i1 = g_pidx[2 * t + 1];
    const float p0 = g_prob[i0];
    const float p1 = g_prob[i1];
    const float4 a0 = reinterpret_cast<const float4*>(g_o  + (size_t)i0 * CDIM)[c4];
    const float4 a1 = reinterpret_cast<const float4*>(g_o2 + (size_t)i0 * CDIM)[c4];
    const float4 a2 = reinterpret_cast<const float4*>(g_o3 + (size_t)i0 * CDIM)[c4];
    const float4 b0 = reinterpret_cast<const float4*>(g_o  + (size_t)i1 * CDIM)[c4];
    const float4 b1 = reinterpret_cast<const float4*>(g_o2 + (size_t)i1 * CDIM)[c4];
    const float4 b2 = reinterpret_cast<const float4*>(g_o3 + (size_t)i1 * CDIM)[c4];
    float4 y;
    y.x = p0 * (a0.x + a1.x + a2.x) + p1 * (b0.x + b1.x + b2.x);
    y.y = p0 * (a0.y + a1.y + a2.y) + p1 * (b0.y + b1.y + b2.y);
    y.z = p0 * (a0.z + a1.z + a2.z) + p1 * (b0.z + b1.z + b2.z);
    y.w = p0 * (a0.w + a1.w + a2.w) + p1 * (b0.w + b1.w + b2.w);
    reinterpret_cast<float4*>(out + (size_t)t * CDIM)[c4] = y;
}

// ---------------- launch ----------------
extern "C" void kernel_launch(void* const* d_in, const int* in_sizes, int n_in,
                              void* d_out, int out_size) {
    const float* x    = (const float*)d_in[0];
    const float* wr   = (const float*)d_in[1];
    const float* wfc  = (const float*)d_in[2];
    const float* bfc  = (const float*)d_in[3];
    const float* wgt  = (const float*)d_in[4];
    const float* bgt  = (const float*)d_in[5];
    const float* wpr  = (const float*)d_in[6];
    const float* bpr  = (const float*)d_in[7];
    float* out = (float*)d_out;

    // REQUIRED: dynamic smem exceeds the 48KB default opt-in
    cudaFuncSetAttribute(gemm1_kernel, cudaFuncAttributeMaxDynamicSharedMemorySize, G1_SMEM_BYTES);
    cudaFuncSetAttribute(gemm2_kernel, cudaFuncAttributeMaxDynamicSharedMemorySize, G2_SMEM_BYTES);

    __half* wfcH; cudaGetSymbolAddress((void**)&wfcH, g_wfcH);
    __half* wgtH; cudaGetSymbolAddress((void**)&wgtH, g_wgtH);
    __half* wprH; cudaGetSymbolAddress((void**)&wprH, g_wprH);

    init_kernel<<<1, 32>>>();
    // fused router + weight convert (router blocks first, convert hides them)
    prepass_kernel<<<RBLKS + 3 * CBLKS_PER, 256>>>(x, wr,
                                                   (const float4*)wfc, (const float4*)wgt,
                                                   (const float4*)wpr,
                                                   (__half2*)wfcH, (__half2*)wgtH, (__half2*)wprH);
    gemm1_kernel<<<dim3(HDIM / 64, CAP / 128, EDIM), 256, G1_SMEM_BYTES>>>(bfc, bgt);
    gemm2_kernel<<<dim3(CDIM / 128, CAP / 128, EDIM * NSPLIT), 256, G2_SMEM_BYTES>>>(bpr);
    combine_kernel<<<NTOK, 192>>>(out);
}

// round 13
// speedup vs baseline: 1.2160x; 1.0170x over previous
#include <cuda_runtime.h>
#include <cuda_fp16.h>
#include <math.h>
#include <stdint.h>

// Problem constants
#define NTOK 2048
#define CDIM 768
#define EDIM 8
#define HDIM 3072
#define CAP  2048

// ---------------- scratch (static device memory; no allocations) ----------------
__device__ __half g_xbuf[(size_t)EDIM * CAP * CDIM];   // gathered activations (fp16)
__device__ __half g_u   [(size_t)EDIM * CAP * HDIM];   // h*silu(g) (fp16)
__device__ __half g_oh  [(size_t)3 * EDIM * CAP * CDIM]; // proj out, 3 split-K parts (fp16)
__device__ __half g_wfcH[(size_t)EDIM * CDIM * HDIM];  // fp16 weights
__device__ __half g_wgtH[(size_t)EDIM * CDIM * HDIM];
__device__ __half g_wprH[(size_t)EDIM * HDIM * CDIM];
__device__ int    g_cnt [EDIM];
__device__ float  g_prob[EDIM * CAP];
__device__ int    g_pidx[2 * NTOK];

#define OH_STRIDE ((size_t)EDIM * CAP * CDIM)

// ---------------- helpers ----------------
__device__ __forceinline__ void mma_f16(float c[4], const unsigned a[4], const unsigned b[2]) {
    asm volatile(
        "mma.sync.aligned.m16n8k16.row.col.f32.f16.f16.f32 "
        "{%0,%1,%2,%3},{%4,%5,%6,%7},{%8,%9},{%0,%1,%2,%3};\n"
        : "+f"(c[0]), "+f"(c[1]), "+f"(c[2]), "+f"(c[3])
        : "r"(a[0]), "r"(a[1]), "r"(a[2]), "r"(a[3]), "r"(b[0]), "r"(b[1]));
}

__device__ __forceinline__ void ldsm_x4(unsigned r[4], uint32_t addr) {
    asm volatile("ldmatrix.sync.aligned.m8n8.x4.shared.b16 {%0,%1,%2,%3}, [%4];"
                 : "=r"(r[0]), "=r"(r[1]), "=r"(r[2]), "=r"(r[3]) : "r"(addr));
}
__device__ __forceinline__ void ldsm_x4t(unsigned r[4], uint32_t addr) {
    asm volatile("ldmatrix.sync.aligned.m8n8.x4.trans.shared.b16 {%0,%1,%2,%3}, [%4];"
                 : "=r"(r[0]), "=r"(r[1]), "=r"(r[2]), "=r"(r[3]) : "r"(addr));
}

__device__ __forceinline__ void cpa16(uint32_t dst, const void* src, int sz) {
    asm volatile("cp.async.cg.shared.global [%0], [%1], 16, %2;"
                 :: "r"(dst), "l"(src), "r"(sz));
}
__device__ __forceinline__ void cpa16u(uint32_t dst, const void* src) {
    asm volatile("cp.async.cg.shared.global [%0], [%1], 16;"
                 :: "r"(dst), "l"(src));
}
__device__ __forceinline__ void cpa_commit() { asm volatile("cp.async.commit_group;"); }
__device__ __forceinline__ void cpa_wait1()  { asm volatile("cp.async.wait_group 1;" ::: "memory"); }
__device__ __forceinline__ void cpa_wait0()  { asm volatile("cp.async.wait_group 0;" ::: "memory"); }

__device__ __forceinline__ uint32_t smem_u32(const void* p) {
    return (uint32_t)__cvta_generic_to_shared(p);
}

// ---------------- kernel 0: init counters ----------------
__global__ void init_kernel() {
    if (threadIdx.x < EDIM) g_cnt[threadIdx.x] = 0;
}

// ---------------- fused pre-pass: router blocks [0,256) + fc/gate weight-convert ----------------
#define WQUARTS (EDIM * CDIM * HDIM / 4)       // float4 per tensor: 4,718,592
#define CBLKS_PER (WQUARTS / 256)              // 18432 blocks per tensor
#define RBLKS (NTOK / 8)                       // 256 router blocks

__global__ __launch_bounds__(256) void prepass_kernel(const float* __restrict__ x,
                                                      const float* __restrict__ wr,
                                                      const float4* __restrict__ wfc,
                                                      const float4* __restrict__ wgt,
                                                      __half2* __restrict__ ofc,
                                                      __half2* __restrict__ ogt) {
    if (blockIdx.x >= RBLKS) {
        // ---- convert portion (fc + gate only; wpr handled in gemm1 prologue) ----
        const int cb = blockIdx.x - RBLKS;
        const int which = cb / CBLKS_PER;
        const size_t i = (size_t)(cb % CBLKS_PER) * 256 + threadIdx.x;
        const float4* src = (which == 0) ? wfc : wgt;
        __half2* dst = (which == 0) ? ofc : ogt;
        float4 v = src[i];
        dst[2 * i + 0] = __floats2half2_rn(v.x, v.y);
        dst[2 * i + 1] = __floats2half2_rn(v.z, v.w);
        return;
    }

    // ---- router portion ----
    const int t = blockIdx.x * 8 + (threadIdx.x >> 5);
    const int lane = threadIdx.x & 31;
    const float* xr = x + (size_t)t * CDIM;

    float acc[EDIM];
#pragma unroll
    for (int e = 0; e < EDIM; e++) acc[e] = 0.f;
#pragma unroll
    for (int j = 0; j < CDIM / 32; j++) {
        int i = lane + 32 * j;
        float xv = xr[i];
        const float4* w4 = reinterpret_cast<const float4*>(wr + (size_t)i * EDIM);
        float4 w0 = w4[0], w1 = w4[1];
        acc[0] += xv * w0.x; acc[1] += xv * w0.y; acc[2] += xv * w0.z; acc[3] += xv * w0.w;
        acc[4] += xv * w1.x; acc[5] += xv * w1.y; acc[6] += xv * w1.z; acc[7] += xv * w1.w;
    }
#pragma unroll
    for (int off = 16; off > 0; off >>= 1) {
#pragma unroll
        for (int e = 0; e < EDIM; e++) acc[e] += __shfl_xor_sync(0xffffffffu, acc[e], off);
    }
    int e0 = 0; float l0 = acc[0];
#pragma unroll
    for (int e = 1; e < EDIM; e++) if (acc[e] > l0) { l0 = acc[e]; e0 = e; }
    int e1 = -1; float l1 = -INFINITY;
#pragma unroll
    for (int e = 0; e < EDIM; e++) if (e != e0 && acc[e] > l1) { l1 = acc[e]; e1 = e; }

    float ex = expf(l1 - l0);
    float p0 = 1.f / (1.f + ex);
    float p1 = ex * p0;

    int s0 = 0, s1 = 0;
    if (lane == 0) {
        s0 = atomicAdd(&g_cnt[e0], 1);
        s1 = atomicAdd(&g_cnt[e1], 1);
        g_prob[e0 * CAP + s0] = p0;
        g_prob[e1 * CAP + s1] = p1;
        g_pidx[2 * t + 0] = e0 * CAP + s0;
        g_pidx[2 * t + 1] = e1 * CAP + s1;
    }
    s0 = __shfl_sync(0xffffffffu, s0, 0);
    s1 = __shfl_sync(0xffffffffu, s1, 0);

    __half2* d0 = reinterpret_cast<__half2*>(g_xbuf + ((size_t)e0 * CAP + s0) * CDIM);
    __half2* d1 = reinterpret_cast<__half2*>(g_xbuf + ((size_t)e1 * CAP + s1) * CDIM);
    const float2* x2 = reinterpret_cast<const float2*>(xr);
#pragma unroll
    for (int j = 0; j < CDIM / 64; j++) {
        int i = lane + 32 * j;
        float2 v = x2[i];
        __half2 h = __floats2half2_rn(v.x, v.y);
        d0[i] = h;
        d1[i] = h;
    }
}

// ======== GEMM1: fused fc+gate, block 128x64(x2), BK=64, fp16 mma, cp.async 2-stage ========
// Prologue: each CTA converts 3 float4/thread of wpr -> wprH (covers tensor exactly:
// 6144 CTAs * 256 thr * 3 = 4,718,592 float4). Runs before early-exit so coverage is
// independent of routing counts. Kernel boundary orders it before gemm2.
#define G1_AH    9216            // halves per A stage
#define G1_BH    4608            // halves per B stage (each matrix)
#define G1_BF0H  (2 * G1_AH)
#define G1_BG0H  (G1_BF0H + 2 * G1_BH)
#define G1_SMEM_BYTES ((G1_BG0H + 2 * G1_BH) * 2)

__global__ __launch_bounds__(256, 2) void gemm1_kernel(const float* __restrict__ bfc,
                                                       const float* __restrict__ bgt,
                                                       const float4* __restrict__ wpr4,
                                                       __half2* __restrict__ wprH2) {
    extern __shared__ __half smh[];
    const int tid = threadIdx.x;

    // ---- wpr convert prologue (ALL CTAs, before any early exit) ----
    {
        size_t cid = ((size_t)blockIdx.z * gridDim.y + blockIdx.y) * gridDim.x + blockIdx.x;
        size_t b = (cid * 256 + tid) * 3;
#pragma unroll
        for (int i = 0; i < 3; i++) {
            float4 v = wpr4[b + i];
            wprH2[2 * (b + i) + 0] = __floats2half2_rn(v.x, v.y);
            wprH2[2 * (b + i) + 1] = __floats2half2_rn(v.z, v.w);
        }
    }

    const int e   = blockIdx.z;
    const int cnt = g_cnt[e];
    const int m0  = blockIdx.y * 128;
    if (m0 >= cnt) return;
    const int n0  = blockIdx.x * 64;

    const __half* Ag = g_xbuf + (size_t)e * CAP * CDIM;
    const __half* B0 = g_wfcH + (size_t)e * CDIM * HDIM;
    const __half* B1 = g_wgtH + (size_t)e * CDIM * HDIM;

    const int lane = tid & 31, wid = tid >> 5;
    const int wm = (wid & 3) * 32, wn = (wid >> 2) * 32;
    const int gq = lane >> 2, tg = lane & 3;
    const int grp = lane >> 3, rin = lane & 7;

    const uint32_t sBase = smem_u32(smh);

    auto load_stage = [&](int buf, int k0) {
#pragma unroll
        for (int i = 0; i < 4; i++) {
            int v = tid + 256 * i, row = v >> 3, c16 = v & 7;
            int sz = (m0 + row < cnt) ? 16 : 0;
            cpa16(sBase + (uint32_t)(buf * G1_AH + row * 72 + c16 * 8) * 2,
                  Ag + (size_t)(m0 + row) * CDIM + k0 + c16 * 8, sz);
        }
#pragma unroll
        for (int i = 0; i < 2; i++) {
            int v = tid + 256 * i, row = v >> 3, c16 = v & 7;
            size_t off = (size_t)(k0 + row) * HDIM + n0 + c16 * 8;
            cpa16u(sBase + (uint32_t)(G1_BF0H + buf * G1_BH + row * 72 + c16 * 8) * 2, B0 + off);
            cpa16u(sBase + (uint32_t)(G1_BG0H + buf * G1_BH + row * 72 + c16 * 8) * 2, B1 + off);
        }
        cpa_commit();
    };

    float cf[2][4][4] = {};
    float cg[2][4][4] = {};

    const int NIT = CDIM / 64;  // 12
    load_stage(0, 0);
    load_stage(1, 64);

#pragma unroll 1
    for (int it = 0; it < NIT; ++it) {
        const int cur = it & 1;
        if (it + 1 < NIT) cpa_wait1(); else cpa_wait0();
        __syncthreads();

        const uint32_t aB  = sBase + (uint32_t)(cur * G1_AH) * 2;
        const uint32_t bfB = sBase + (uint32_t)(G1_BF0H + cur * G1_BH) * 2;
        const uint32_t bgB = sBase + (uint32_t)(G1_BG0H + cur * G1_BH) * 2;

        unsigned uA[2][2][4], uBf[2][4][2], uBg[2][4][2];

        auto ldfrag = [&](int ks, int s) {
            const int kb = ks * 16;
#pragma unroll
            for (int mt = 0; mt < 2; mt++) {
                int r = wm + mt * 16 + (grp & 1) * 8 + rin;
                ldsm_x4(uA[s][mt], aB + (uint32_t)((r * 72 + kb + (grp >> 1) * 8) * 2));
            }
#pragma unroll
            for (int p = 0; p < 2; p++) {
                int kr = kb + (grp & 1) * 8 + rin;
                int cc = wn + p * 16 + (grp >> 1) * 8;
                unsigned r4[4];
                ldsm_x4t(r4, bfB + (uint32_t)((kr * 72 + cc) * 2));
                uBf[s][2 * p + 0][0] = r4[0]; uBf[s][2 * p + 0][1] = r4[1];
                uBf[s][2 * p + 1][0] = r4[2]; uBf[s][2 * p + 1][1] = r4[3];
                ldsm_x4t(r4, bgB + (uint32_t)((kr * 72 + cc) * 2));
                uBg[s][2 * p + 0][0] = r4[0]; uBg[s][2 * p + 0][1] = r4[1];
                uBg[s][2 * p + 1][0] = r4[2]; uBg[s][2 * p + 1][1] = r4[3];
            }
        };

        ldfrag(0, 0);
#pragma unroll
        for (int ks = 0; ks < 4; ks++) {
            const int s = ks & 1;
            if (ks < 3) ldfrag(ks + 1, s ^ 1);
#pragma unroll
            for (int mt = 0; mt < 2; mt++)
#pragma unroll
                for (int nt = 0; nt < 4; nt++) {
                    mma_f16(cf[mt][nt], uA[s][mt], uBf[s][nt]);
                    mma_f16(cg[mt][nt], uA[s][mt], uBg[s][nt]);
                }
        }
        __syncthreads();
        if (it + 2 < NIT) load_stage(cur, (it + 2) * 64);
    }

    // epilogue: u = (h+bfc) * silu(g+bg) -> fp16
    __half* U = g_u + (size_t)e * CAP * HDIM;
#pragma unroll
    for (int mt = 0; mt < 2; mt++) {
#pragma unroll
        for (int nt = 0; nt < 4; nt++) {
            int col = n0 + wn + nt * 8 + tg * 2;
            float bf0 = bfc[(size_t)e * HDIM + col], bf1 = bfc[(size_t)e * HDIM + col + 1];
            float bg0 = bgt[(size_t)e * HDIM + col], bg1 = bgt[(size_t)e * HDIM + col + 1];
            int r0 = m0 + wm + mt * 16 + gq;
            if (r0 < cnt) {
                float h0 = cf[mt][nt][0] + bf0, h1 = cf[mt][nt][1] + bf1;
                float q0 = cg[mt][nt][0] + bg0, q1 = cg[mt][nt][1] + bg1;
                float u0 = h0 * (q0 / (1.f + expf(-q0)));
                float u1 = h1 * (q1 / (1.f + expf(-q1)));
                *reinterpret_cast<__half2*>(U + (size_t)r0 * HDIM + col) = __floats2half2_rn(u0, u1);
            }
            int r1 = r0 + 8;
            if (r1 < cnt) {
                float h0 = cf[mt][nt][2] + bf0, h1 = cf[mt][nt][3] + bf1;
                float q0 = cg[mt][nt][2] + bg0, q1 = cg[mt][nt][3] + bg1;
                float u0 = h0 * (q0 / (1.f + expf(-q0)));
                float u1 = h1 * (q1 / (1.f + expf(-q1)));
                *reinterpret_cast<__half2*>(U + (size_t)r1 * HDIM + col) = __floats2half2_rn(u0, u1);
            }
        }
    }
}

// ======== GEMM2: proj, block 128x128, warp 64x32, BK=64, fp16 mma, 2-stage, split-K=3 ========
#define G2_AH   9216
#define G2_BH   8704
#define G2_B0H  (2 * G2_AH)
#define G2_SMEM_BYTES ((G2_B0H + 2 * G2_BH) * 2)
#define NSPLIT 3
#define SPLITK (HDIM / NSPLIT)   // 1024

__global__ __launch_bounds__(256, 2) void gemm2_kernel(const float* __restrict__ bpr) {
    extern __shared__ __half smh[];
    const int e     = blockIdx.z / NSPLIT;
    const int split = blockIdx.z % NSPLIT;
    const int cnt   = g_cnt[e];
    const int m0    = blockIdx.y * 128;
    if (m0 >= cnt) return;
    const int n0    = blockIdx.x * 128;
    const int kbase = split * SPLITK;

    const __half* Ag = g_u + (size_t)e * CAP * HDIM + kbase;
    const __half* Bp = g_wprH + (size_t)e * HDIM * CDIM + (size_t)kbase * CDIM;

    const int tid = threadIdx.x, lane = tid & 31, wid = tid >> 5;
    const int wm = (wid & 1) * 64, wn = (wid >> 1) * 32;
    const int gq = lane >> 2, tg = lane & 3;
    const int grp = lane >> 3, rin = lane & 7;

    const uint32_t sBase = smem_u32(smh);

    auto load_stage = [&](int buf, int k0) {
#pragma unroll
        for (int i = 0; i < 4; i++) {
            int v = tid + 256 * i, row = v >> 3, c16 = v & 7;
            int sz = (m0 + row < cnt) ? 16 : 0;
            cpa16(sBase + (uint32_t)(buf * G2_AH + row * 72 + c16 * 8) * 2,
                  Ag + (size_t)(m0 + row) * HDIM + k0 + c16 * 8, sz);
        }
#pragma unroll
        for (int i = 0; i < 4; i++) {
            int v = tid + 256 * i, row = v >> 4, c16 = v & 15;
            cpa16u(sBase + (uint32_t)(G2_B0H + buf * G2_BH + row * 136 + c16 * 8) * 2,
                   Bp + (size_t)(k0 + row) * CDIM + n0 + c16 * 8);
        }
        cpa_commit();
    };

    float acc[4][4][4] = {};

    const int NIT = SPLITK / 64;  // 16
    load_stage(0, 0);
    load_stage(1, 64);

#pragma unroll 1
    for (int it = 0; it < NIT; ++it) {
        const int cur = it & 1;
        if (it + 1 < NIT) cpa_wait1(); else cpa_wait0();
        __syncthreads();

        const uint32_t aB = sBase + (uint32_t)(cur * G2_AH) * 2;
        const uint32_t bB = sBase + (uint32_t)(G2_B0H + cur * G2_BH) * 2;

        unsigned uA[2][4][4], uB[2][4][2];

        auto ldfrag = [&](int ks, int s) {
            const int kb = ks * 16;
#pragma unroll
            for (int mt = 0; mt < 4; mt++) {
                int r = wm + mt * 16 + (grp & 1) * 8 + rin;
                ldsm_x4(uA[s][mt], aB + (uint32_t)((r * 72 + kb + (grp >> 1) * 8) * 2));
            }
            {
                int kr = kb + (grp & 1) * 8 + rin;
#pragma unroll
                for (int p = 0; p < 2; p++) {
                    int cc = wn + p * 16 + (grp >> 1) * 8;
                    unsigned r4[4];
                    ldsm_x4t(r4, bB + (uint32_t)((kr * 136 + cc) * 2));
                    uB[s][2 * p + 0][0] = r4[0]; uB[s][2 * p + 0][1] = r4[1];
                    uB[s][2 * p + 1][0] = r4[2]; uB[s][2 * p + 1][1] = r4[3];
                }
            }
        };

        ldfrag(0, 0);
#pragma unroll
        for (int ks = 0; ks < 4; ks++) {
            const int s = ks & 1;
            if (ks < 3) ldfrag(ks + 1, s ^ 1);
#pragma unroll
            for (int mt = 0; mt < 4; mt++)
#pragma unroll
                for (int nt = 0; nt < 4; nt++)
                    mma_f16(acc[mt][nt], uA[s][mt], uB[s][nt]);
        }
        __syncthreads();
        if (it + 2 < NIT) load_stage(cur, (it + 2) * 64);
    }

    // fp16 partial store (split buffers summed in combine)
    __half* O = g_oh + (size_t)split * OH_STRIDE + (size_t)e * CAP * CDIM;
#pragma unroll
    for (int mt = 0; mt < 4; mt++) {
#pragma unroll
        for (int nt = 0; nt < 4; nt++) {
            int col = n0 + wn + nt * 8 + tg * 2;
            float b0 = 0.f, b1 = 0.f;
            if (split == 0) {
                b0 = bpr[(size_t)e * CDIM + col];
                b1 = bpr[(size_t)e * CDIM + col + 1];
            }
            int r0 = m0 + wm + mt * 16 + gq;
            if (r0 < cnt) {
                *reinterpret_cast<__half2*>(O + (size_t)r0 * CDIM + col) =
                    __floats2half2_rn(acc[mt][nt][0] + b0, acc[mt][nt][1] + b1);
            }
            int r1 = r0 + 8;
            if (r1 < cnt) {
                *reinterpret_cast<__half2*>(O + (size_t)r1 * CDIM + col) =
                    __floats2half2_rn(acc[mt][nt][2] + b0, acc[mt][nt][3] + b1);
            }
        }
    }
}

// ---------------- kernel 4: deterministic combine (sums 3 fp16 split parts) ----------------
__global__ __launch_bounds__(192) void combine_kernel(float* __restrict__ out) {
    const int t = blockIdx.x;
    const int c4 = threadIdx.x;            // handles cols [4*c4, 4*c4+4)
    const int i0 = g_pidx[2 * t + 0];
    const int i1 = g_pidx[2 * t + 1];
    const float p0 = g_prob[i0];
    const float p1 = g_prob[i1];

    float s0[4] = {0.f, 0.f, 0.f, 0.f};
    float s1[4] = {0.f, 0.f, 0.f, 0.f};
#pragma unroll
    for (int sp = 0; sp < 3; sp++) {
        const __half2* A = reinterpret_cast<const __half2*>(
            g_oh + (size_t)sp * OH_STRIDE + (size_t)i0 * CDIM);
        const __half2* B = reinterpret_cast<const __half2*>(
            g_oh + (size_t)sp * OH_STRIDE + (size_t)i1 * CDIM);
        float2 a0 = __half22float2(A[2 * c4 + 0]);
        float2 a1 = __half22float2(A[2 * c4 + 1]);
        float2 b0 = __half22float2(B[2 * c4 + 0]);
        float2 b1 = __half22float2(B[2 * c4 + 1]);
        s0[0] += a0.x; s0[1] += a0.y; s0[2] += a1.x; s0[3] += a1.y;
        s1[0] += b0.x; s1[1] += b0.y; s1[2] += b1.x; s1[3] += b1.y;
    }
    float4 y;
    y.x = p0 * s0[0] + p1 * s1[0];
    y.y = p0 * s0[1] + p1 * s1[1];
    y.z = p0 * s0[2] + p1 * s1[2];
    y.w = p0 * s0[3] + p1 * s1[3];
    reinterpret_cast<float4*>(out + (size_t)t * CDIM)[c4] = y;
}

// ---------------- launch ----------------
extern "C" void kernel_launch(void* const* d_in, const int* in_sizes, int n_in,
                              void* d_out, int out_size) {
    const float* x    = (const float*)d_in[0];
    const float* wr   = (const float*)d_in[1];
    const float* wfc  = (const float*)d_in[2];
    const float* bfc  = (const float*)d_in[3];
    const float* wgt  = (const float*)d_in[4];
    const float* bgt  = (const float*)d_in[5];
    const float* wpr  = (const float*)d_in[6];
    const float* bpr  = (const float*)d_in[7];
    float* out = (float*)d_out;

    // REQUIRED: dynamic smem exceeds the 48KB default opt-in
    cudaFuncSetAttribute(gemm1_kernel, cudaFuncAttributeMaxDynamicSharedMemorySize, G1_SMEM_BYTES);
    cudaFuncSetAttribute(gemm2_kernel, cudaFuncAttributeMaxDynamicSharedMemorySize, G2_SMEM_BYTES);

    __half* wfcH; cudaGetSymbolAddress((void**)&wfcH, g_wfcH);
    __half* wgtH; cudaGetSymbolAddress((void**)&wgtH, g_wgtH);
    __half* wprH; cudaGetSymbolAddress((void**)&wprH, g_wprH);

    init_kernel<<<1, 32>>>();
    // fused router + fc/gate weight convert (router blocks first, convert hides them)
    prepass_kernel<<<RBLKS + 2 * CBLKS_PER, 256>>>(x, wr,
                                                   (const float4*)wfc, (const float4*)wgt,
                                                   (__half2*)wfcH, (__half2*)wgtH);
    // gemm1 also converts wpr in its prologue (exact coverage: 6144*256*3 float4)
    gemm1_kernel<<<dim3(HDIM / 64, CAP / 128, EDIM), 256, G1_SMEM_BYTES>>>(
        bfc, bgt, (const float4*)wpr, (__half2*)wprH);
    gemm2_kernel<<<dim3(CDIM / 128, CAP / 128, EDIM * NSPLIT), 256, G2_SMEM_BYTES>>>(bpr);
    combine_kernel<<<NTOK, 192>>>(out);
}

// round 14
// speedup vs baseline: 1.2235x; 1.0062x over previous
#include <cuda_runtime.h>
#include <cuda_fp16.h>
#include <math.h>
#include <stdint.h>

// Problem constants
#define NTOK 2048
#define CDIM 768
#define EDIM 8
#define HDIM 3072
#define CAP  2048

// ---------------- scratch (static device memory; no allocations) ----------------
__device__ __half g_xbuf[(size_t)EDIM * CAP * CDIM];   // gathered activations (fp16)
__device__ __half g_u   [(size_t)EDIM * CAP * HDIM];   // h*silu(g) (fp16)
__device__ __half g_oh  [(size_t)3 * EDIM * CAP * CDIM]; // proj out, 3 split-K parts (fp16)
__device__ __half g_wfcH[(size_t)EDIM * CDIM * HDIM];  // fp16 weights
__device__ __half g_wgtH[(size_t)EDIM * CDIM * HDIM];
__device__ __half g_wprH[(size_t)EDIM * HDIM * CDIM];
__device__ int    g_cnt [EDIM];                        // zero at load; re-zeroed by combine
__device__ float  g_prob[EDIM * CAP];
__device__ int    g_pidx[2 * NTOK];

#define OH_STRIDE ((size_t)EDIM * CAP * CDIM)

// ---------------- helpers ----------------
__device__ __forceinline__ void mma_f16(float c[4], const unsigned a[4], const unsigned b[2]) {
    asm volatile(
        "mma.sync.aligned.m16n8k16.row.col.f32.f16.f16.f32 "
        "{%0,%1,%2,%3},{%4,%5,%6,%7},{%8,%9},{%0,%1,%2,%3};\n"
        : "+f"(c[0]), "+f"(c[1]), "+f"(c[2]), "+f"(c[3])
        : "r"(a[0]), "r"(a[1]), "r"(a[2]), "r"(a[3]), "r"(b[0]), "r"(b[1]));
}

__device__ __forceinline__ void ldsm_x4(unsigned r[4], uint32_t addr) {
    asm volatile("ldmatrix.sync.aligned.m8n8.x4.shared.b16 {%0,%1,%2,%3}, [%4];"
                 : "=r"(r[0]), "=r"(r[1]), "=r"(r[2]), "=r"(r[3]) : "r"(addr));
}
__device__ __forceinline__ void ldsm_x4t(unsigned r[4], uint32_t addr) {
    asm volatile("ldmatrix.sync.aligned.m8n8.x4.trans.shared.b16 {%0,%1,%2,%3}, [%4];"
                 : "=r"(r[0]), "=r"(r[1]), "=r"(r[2]), "=r"(r[3]) : "r"(addr));
}

__device__ __forceinline__ void cpa16(uint32_t dst, const void* src, int sz) {
    asm volatile("cp.async.cg.shared.global [%0], [%1], 16, %2;"
                 :: "r"(dst), "l"(src), "r"(sz));
}
__device__ __forceinline__ void cpa16u(uint32_t dst, const void* src) {
    asm volatile("cp.async.cg.shared.global [%0], [%1], 16;"
                 :: "r"(dst), "l"(src));
}
__device__ __forceinline__ void cpa_commit() { asm volatile("cp.async.commit_group;"); }
__device__ __forceinline__ void cpa_wait1()  { asm volatile("cp.async.wait_group 1;" ::: "memory"); }
__device__ __forceinline__ void cpa_wait0()  { asm volatile("cp.async.wait_group 0;" ::: "memory"); }

__device__ __forceinline__ uint32_t smem_u32(const void* p) {
    return (uint32_t)__cvta_generic_to_shared(p);
}

// ---------------- fused pre-pass: router blocks [0,256) + fc/gate weight-convert ----------------
#define WQUARTS (EDIM * CDIM * HDIM / 4)       // float4 per tensor: 4,718,592
#define CBLKS_PER (WQUARTS / 256)              // 18432 blocks per tensor
#define RBLKS (NTOK / 8)                       // 256 router blocks

__global__ __launch_bounds__(256) void prepass_kernel(const float* __restrict__ x,
                                                      const float* __restrict__ wr,
                                                      const float4* __restrict__ wfc,
                                                      const float4* __restrict__ wgt,
                                                      __half2* __restrict__ ofc,
                                                      __half2* __restrict__ ogt) {
    if (blockIdx.x >= RBLKS) {
        // ---- convert portion (fc + gate only; wpr handled in gemm1 prologue) ----
        const int cb = blockIdx.x - RBLKS;
        const int which = cb / CBLKS_PER;
        const size_t i = (size_t)(cb % CBLKS_PER) * 256 + threadIdx.x;
        const float4* src = (which == 0) ? wfc : wgt;
        __half2* dst = (which == 0) ? ofc : ogt;
        float4 v = src[i];
        dst[2 * i + 0] = __floats2half2_rn(v.x, v.y);
        dst[2 * i + 1] = __floats2half2_rn(v.z, v.w);
        return;
    }

    // ---- router portion ----
    const int t = blockIdx.x * 8 + (threadIdx.x >> 5);
    const int lane = threadIdx.x & 31;
    const float* xr = x + (size_t)t * CDIM;

    float acc[EDIM];
#pragma unroll
    for (int e = 0; e < EDIM; e++) acc[e] = 0.f;
#pragma unroll
    for (int j = 0; j < CDIM / 32; j++) {
        int i = lane + 32 * j;
        float xv = xr[i];
        const float4* w4 = reinterpret_cast<const float4*>(wr + (size_t)i * EDIM);
        float4 w0 = w4[0], w1 = w4[1];
        acc[0] += xv * w0.x; acc[1] += xv * w0.y; acc[2] += xv * w0.z; acc[3] += xv * w0.w;
        acc[4] += xv * w1.x; acc[5] += xv * w1.y; acc[6] += xv * w1.z; acc[7] += xv * w1.w;
    }
#pragma unroll
    for (int off = 16; off > 0; off >>= 1) {
#pragma unroll
        for (int e = 0; e < EDIM; e++) acc[e] += __shfl_xor_sync(0xffffffffu, acc[e], off);
    }
    int e0 = 0; float l0 = acc[0];
#pragma unroll
    for (int e = 1; e < EDIM; e++) if (acc[e] > l0) { l0 = acc[e]; e0 = e; }
    int e1 = -1; float l1 = -INFINITY;
#pragma unroll
    for (int e = 0; e < EDIM; e++) if (e != e0 && acc[e] > l1) { l1 = acc[e]; e1 = e; }

    float ex = expf(l1 - l0);
    float p0 = 1.f / (1.f + ex);
    float p1 = ex * p0;

    int s0 = 0, s1 = 0;
    if (lane == 0) {
        s0 = atomicAdd(&g_cnt[e0], 1);
        s1 = atomicAdd(&g_cnt[e1], 1);
        g_prob[e0 * CAP + s0] = p0;
        g_prob[e1 * CAP + s1] = p1;
        g_pidx[2 * t + 0] = e0 * CAP + s0;
        g_pidx[2 * t + 1] = e1 * CAP + s1;
    }
    s0 = __shfl_sync(0xffffffffu, s0, 0);
    s1 = __shfl_sync(0xffffffffu, s1, 0);

    __half2* d0 = reinterpret_cast<__half2*>(g_xbuf + ((size_t)e0 * CAP + s0) * CDIM);
    __half2* d1 = reinterpret_cast<__half2*>(g_xbuf + ((size_t)e1 * CAP + s1) * CDIM);
    const float2* x2 = reinterpret_cast<const float2*>(xr);
#pragma unroll
    for (int j = 0; j < CDIM / 64; j++) {
        int i = lane + 32 * j;
        float2 v = x2[i];
        __half2 h = __floats2half2_rn(v.x, v.y);
        d0[i] = h;
        d1[i] = h;
    }
}

// ======== GEMM1: fused fc+gate, block 128x64(x2), BK=64, fp16 mma, cp.async 2-stage ========
// Prologue: each CTA converts 3 float4/thread of wpr -> wprH (exact coverage:
// 6144 CTAs * 256 thr * 3 = 4,718,592 float4), before any early exit.
#define G1_AH    9216            // halves per A stage
#define G1_BH    4608            // halves per B stage (each matrix)
#define G1_BF0H  (2 * G1_AH)
#define G1_BG0H  (G1_BF0H + 2 * G1_BH)
#define G1_SMEM_BYTES ((G1_BG0H + 2 * G1_BH) * 2)

__global__ __launch_bounds__(256, 2) void gemm1_kernel(const float* __restrict__ bfc,
                                                       const float* __restrict__ bgt,
                                                       const float4* __restrict__ wpr4,
                                                       __half2* __restrict__ wprH2) {
    extern __shared__ __half smh[];
    const int tid = threadIdx.x;

    // ---- wpr convert prologue (ALL CTAs, before any early exit) ----
    {
        size_t cid = ((size_t)blockIdx.z * gridDim.y + blockIdx.y) * gridDim.x + blockIdx.x;
        size_t b = (cid * 256 + tid) * 3;
#pragma unroll
        for (int i = 0; i < 3; i++) {
            float4 v = wpr4[b + i];
            wprH2[2 * (b + i) + 0] = __floats2half2_rn(v.x, v.y);
            wprH2[2 * (b + i) + 1] = __floats2half2_rn(v.z, v.w);
        }
    }

    const int e   = blockIdx.z;
    const int cnt = g_cnt[e];
    const int m0  = blockIdx.y * 128;
    if (m0 >= cnt) return;
    const int n0  = blockIdx.x * 64;

    const __half* Ag = g_xbuf + (size_t)e * CAP * CDIM;
    const __half* B0 = g_wfcH + (size_t)e * CDIM * HDIM;
    const __half* B1 = g_wgtH + (size_t)e * CDIM * HDIM;

    const int lane = tid & 31, wid = tid >> 5;
    const int wm = (wid & 3) * 32, wn = (wid >> 2) * 32;
    const int gq = lane >> 2, tg = lane & 3;
    const int grp = lane >> 3, rin = lane & 7;

    const uint32_t sBase = smem_u32(smh);

    auto load_stage = [&](int buf, int k0) {
#pragma unroll
        for (int i = 0; i < 4; i++) {
            int v = tid + 256 * i, row = v >> 3, c16 = v & 7;
            int sz = (m0 + row < cnt) ? 16 : 0;
            cpa16(sBase + (uint32_t)(buf * G1_AH + row * 72 + c16 * 8) * 2,
                  Ag + (size_t)(m0 + row) * CDIM + k0 + c16 * 8, sz);
        }
#pragma unroll
        for (int i = 0; i < 2; i++) {
            int v = tid + 256 * i, row = v >> 3, c16 = v & 7;
            size_t off = (size_t)(k0 + row) * HDIM + n0 + c16 * 8;
            cpa16u(sBase + (uint32_t)(G1_BF0H + buf * G1_BH + row * 72 + c16 * 8) * 2, B0 + off);
            cpa16u(sBase + (uint32_t)(G1_BG0H + buf * G1_BH + row * 72 + c16 * 8) * 2, B1 + off);
        }
        cpa_commit();
    };

    float cf[2][4][4] = {};
    float cg[2][4][4] = {};

    const int NIT = CDIM / 64;  // 12
    load_stage(0, 0);
    load_stage(1, 64);

#pragma unroll 1
    for (int it = 0; it < NIT; ++it) {
        const int cur = it & 1;
        if (it + 1 < NIT) cpa_wait1(); else cpa_wait0();
        __syncthreads();

        const uint32_t aB  = sBase + (uint32_t)(cur * G1_AH) * 2;
        const uint32_t bfB = sBase + (uint32_t)(G1_BF0H + cur * G1_BH) * 2;
        const uint32_t bgB = sBase + (uint32_t)(G1_BG0H + cur * G1_BH) * 2;

        unsigned uA[2][2][4], uBf[2][4][2], uBg[2][4][2];

        auto ldfrag = [&](int ks, int s) {
            const int kb = ks * 16;
#pragma unroll
            for (int mt = 0; mt < 2; mt++) {
                int r = wm + mt * 16 + (grp & 1) * 8 + rin;
                ldsm_x4(uA[s][mt], aB + (uint32_t)((r * 72 + kb + (grp >> 1) * 8) * 2));
            }
#pragma unroll
            for (int p = 0; p < 2; p++) {
                int kr = kb + (grp & 1) * 8 + rin;
                int cc = wn + p * 16 + (grp >> 1) * 8;
                unsigned r4[4];
                ldsm_x4t(r4, bfB + (uint32_t)((kr * 72 + cc) * 2));
                uBf[s][2 * p + 0][0] = r4[0]; uBf[s][2 * p + 0][1] = r4[1];
                uBf[s][2 * p + 1][0] = r4[2]; uBf[s][2 * p + 1][1] = r4[3];
                ldsm_x4t(r4, bgB + (uint32_t)((kr * 72 + cc) * 2));
                uBg[s][2 * p + 0][0] = r4[0]; uBg[s][2 * p + 0][1] = r4[1];
                uBg[s][2 * p + 1][0] = r4[2]; uBg[s][2 * p + 1][1] = r4[3];
            }
        };

        ldfrag(0, 0);
#pragma unroll
        for (int ks = 0; ks < 4; ks++) {
            const int s = ks & 1;
            if (ks < 3) ldfrag(ks + 1, s ^ 1);
#pragma unroll
            for (int mt = 0; mt < 2; mt++)
#pragma unroll
                for (int nt = 0; nt < 4; nt++) {
                    mma_f16(cf[mt][nt], uA[s][mt], uBf[s][nt]);
                    mma_f16(cg[mt][nt], uA[s][mt], uBg[s][nt]);
                }
        }
        __syncthreads();
        if (it + 2 < NIT) load_stage(cur, (it + 2) * 64);
    }

    // epilogue: u = (h+bfc) * silu(g+bg) -> fp16
    __half* U = g_u + (size_t)e * CAP * HDIM;
#pragma unroll
    for (int mt = 0; mt < 2; mt++) {
#pragma unroll
        for (int nt = 0; nt < 4; nt++) {
            int col = n0 + wn + nt * 8 + tg * 2;
            float bf0 = bfc[(size_t)e * HDIM + col], bf1 = bfc[(size_t)e * HDIM + col + 1];
            float bg0 = bgt[(size_t)e * HDIM + col], bg1 = bgt[(size_t)e * HDIM + col + 1];
            int r0 = m0 + wm + mt * 16 + gq;
            if (r0 < cnt) {
                float h0 = cf[mt][nt][0] + bf0, h1 = cf[mt][nt][1] + bf1;
                float q0 = cg[mt][nt][0] + bg0, q1 = cg[mt][nt][1] + bg1;
                float u0 = h0 * (q0 / (1.f + expf(-q0)));
                float u1 = h1 * (q1 / (1.f + expf(-q1)));
                *reinterpret_cast<__half2*>(U + (size_t)r0 * HDIM + col) = __floats2half2_rn(u0, u1);
            }
            int r1 = r0 + 8;
            if (r1 < cnt) {
                float h0 = cf[mt][nt][2] + bf0, h1 = cf[mt][nt][3] + bf1;
                float q0 = cg[mt][nt][2] + bg0, q1 = cg[mt][nt][3] + bg1;
                float u0 = h0 * (q0 / (1.f + expf(-q0)));
                float u1 = h1 * (q1 / (1.f + expf(-q1)));
                *reinterpret_cast<__half2*>(U + (size_t)r1 * HDIM + col) = __floats2half2_rn(u0, u1);
            }
        }
    }
}

// ======== GEMM2: proj, block 128x128, warp 64x32, BK=64, fp16 mma, 2-stage, split-K=3 ========
#define G2_AH   9216
#define G2_BH   8704
#define G2_B0H  (2 * G2_AH)
#define G2_SMEM_BYTES ((G2_B0H + 2 * G2_BH) * 2)
#define NSPLIT 3
#define SPLITK (HDIM / NSPLIT)   // 1024

__global__ __launch_bounds__(256, 2) void gemm2_kernel(const float* __restrict__ bpr) {
    extern __shared__ __half smh[];
    const int e     = blockIdx.z / NSPLIT;
    const int split = blockIdx.z % NSPLIT;
    const int cnt   = g_cnt[e];
    const int m0    = blockIdx.y * 128;
    if (m0 >= cnt) return;
    const int n0    = blockIdx.x * 128;
    const int kbase = split * SPLITK;

    const __half* Ag = g_u + (size_t)e * CAP * HDIM + kbase;
    const __half* Bp = g_wprH + (size_t)e * HDIM * CDIM + (size_t)kbase * CDIM;

    const int tid = threadIdx.x, lane = tid & 31, wid = tid >> 5;
    const int wm = (wid & 1) * 64, wn = (wid >> 1) * 32;
    const int gq = lane >> 2, tg = lane & 3;
    const int grp = lane >> 3, rin = lane & 7;

    const uint32_t sBase = smem_u32(smh);

    auto load_stage = [&](int buf, int k0) {
#pragma unroll
        for (int i = 0; i < 4; i++) {
            int v = tid + 256 * i, row = v >> 3, c16 = v & 7;
            int sz = (m0 + row < cnt) ? 16 : 0;
            cpa16(sBase + (uint32_t)(buf * G2_AH + row * 72 + c16 * 8) * 2,
                  Ag + (size_t)(m0 + row) * HDIM + k0 + c16 * 8, sz);
        }
#pragma unroll
        for (int i = 0; i < 4; i++) {
            int v = tid + 256 * i, row = v >> 4, c16 = v & 15;
            cpa16u(sBase + (uint32_t)(G2_B0H + buf * G2_BH + row * 136 + c16 * 8) * 2,
                   Bp + (size_t)(k0 + row) * CDIM + n0 + c16 * 8);
        }
        cpa_commit();
    };

    float acc[4][4][4] = {};

    const int NIT = SPLITK / 64;  // 16
    load_stage(0, 0);
    load_stage(1, 64);

#pragma unroll 1
    for (int it = 0; it < NIT; ++it) {
        const int cur = it & 1;
        if (it + 1 < NIT) cpa_wait1(); else cpa_wait0();
        __syncthreads();

        const uint32_t aB = sBase + (uint32_t)(cur * G2_AH) * 2;
        const uint32_t bB = sBase + (uint32_t)(G2_B0H + cur * G2_BH) * 2;

        unsigned uA[2][4][4], uB[2][4][2];

        auto ldfrag = [&](int ks, int s) {
            const int kb = ks * 16;
#pragma unroll
            for (int mt = 0; mt < 4; mt++) {
                int r = wm + mt * 16 + (grp & 1) * 8 + rin;
                ldsm_x4(uA[s][mt], aB + (uint32_t)((r * 72 + kb + (grp >> 1) * 8) * 2));
            }
            {
                int kr = kb + (grp & 1) * 8 + rin;
#pragma unroll
                for (int p = 0; p < 2; p++) {
                    int cc = wn + p * 16 + (grp >> 1) * 8;
                    unsigned r4[4];
                    ldsm_x4t(r4, bB + (uint32_t)((kr * 136 + cc) * 2));
                    uB[s][2 * p + 0][0] = r4[0]; uB[s][2 * p + 0][1] = r4[1];
                    uB[s][2 * p + 1][0] = r4[2]; uB[s][2 * p + 1][1] = r4[3];
                }
            }
        };

        ldfrag(0, 0);
#pragma unroll
        for (int ks = 0; ks < 4; ks++) {
            const int s = ks & 1;
            if (ks < 3) ldfrag(ks + 1, s ^ 1);
#pragma unroll
            for (int mt = 0; mt < 4; mt++)
#pragma unroll
                for (int nt = 0; nt < 4; nt++)
                    mma_f16(acc[mt][nt], uA[s][mt], uB[s][nt]);
        }
        __syncthreads();
        if (it + 2 < NIT) load_stage(cur, (it + 2) * 64);
    }

    // fp16 partial store (split buffers summed in combine)
    __half* O = g_oh + (size_t)split * OH_STRIDE + (size_t)e * CAP * CDIM;
#pragma unroll
    for (int mt = 0; mt < 4; mt++) {
#pragma unroll
        for (int nt = 0; nt < 4; nt++) {
            int col = n0 + wn + nt * 8 + tg * 2;
            float b0 = 0.f, b1 = 0.f;
            if (split == 0) {
                b0 = bpr[(size_t)e * CDIM + col];
                b1 = bpr[(size_t)e * CDIM + col + 1];
            }
            int r0 = m0 + wm + mt * 16 + gq;
            if (r0 < cnt) {
                *reinterpret_cast<__half2*>(O + (size_t)r0 * CDIM + col) =
                    __floats2half2_rn(acc[mt][nt][0] + b0, acc[mt][nt][1] + b1);
            }
            int r1 = r0 + 8;
            if (r1 < cnt) {
                *reinterpret_cast<__half2*>(O + (size_t)r1 * CDIM + col) =
                    __floats2half2_rn(acc[mt][nt][2] + b0, acc[mt][nt][3] + b1);
            }
        }
    }
}

// ---------------- kernel 4: deterministic combine (sums 3 fp16 split parts) ----------------
// Also re-zeroes g_cnt for the next graph replay (combine is the last kernel;
// g_cnt starts zero-initialized at module load, so every launch sees zeros).
__global__ __launch_bounds__(192) void combine_kernel(float* __restrict__ out) {
    const int t = blockIdx.x;
    const int c4 = threadIdx.x;            // handles cols [4*c4, 4*c4+4)
    const int i0 = g_pidx[2 * t + 0];
    const int i1 = g_pidx[2 * t + 1];
    const float p0 = g_prob[i0];
    const float p1 = g_prob[i1];

    float s0[4] = {0.f, 0.f, 0.f, 0.f};
    float s1[4] = {0.f, 0.f, 0.f, 0.f};
#pragma unroll
    for (int sp = 0; sp < 3; sp++) {
        const __half2* A = reinterpret_cast<const __half2*>(
            g_oh + (size_t)sp * OH_STRIDE + (size_t)i0 * CDIM);
        const __half2* B = reinterpret_cast<const __half2*>(
            g_oh + (size_t)sp * OH_STRIDE + (size_t)i1 * CDIM);
        float2 a0 = __half22float2(A[2 * c4 + 0]);
        float2 a1 = __half22float2(A[2 * c4 + 1]);
        float2 b0 = __half22float2(B[2 * c4 + 0]);
        float2 b1 = __half22float2(B[2 * c4 + 1]);
        s0[0] += a0.x; s0[1] += a0.y; s0[2] += a1.x; s0[3] += a1.y;
        s1[0] += b0.x; s1[1] += b0.y; s1[2] += b1.x; s1[3] += b1.y;
    }
    float4 y;
    y.x = p0 * s0[0] + p1 * s1[0];
    y.y = p0 * s0[1] + p1 * s1[1];
    y.z = p0 * s0[2] + p1 * s1[2];
    y.w = p0 * s0[3] + p1 * s1[3];
    reinterpret_cast<float4*>(out + (size_t)t * CDIM)[c4] = y;

    // reset expert counters for the next launch (deterministic: always runs)
    if (blockIdx.x == 0 && threadIdx.x < EDIM) g_cnt[threadIdx.x] = 0;
}

// ---------------- launch ----------------
extern "C" void kernel_launch(void* const* d_in, const int* in_sizes, int n_in,
                              void* d_out, int out_size) {
    const float* x    = (const float*)d_in[0];
    const float* wr   = (const float*)d_in[1];
    const float* wfc  = (const float*)d_in[2];
    const float* bfc  = (const float*)d_in[3];
    const float* wgt  = (const float*)d_in[4];
    const float* bgt  = (const float*)d_in[5];
    const float* wpr  = (const float*)d_in[6];
    const float* bpr  = (const float*)d_in[7];
    float* out = (float*)d_out;

    // REQUIRED: dynamic smem exceeds the 48KB default opt-in
    cudaFuncSetAttribute(gemm1_kernel, cudaFuncAttributeMaxDynamicSharedMemorySize, G1_SMEM_BYTES);
    cudaFuncSetAttribute(gemm2_kernel, cudaFuncAttributeMaxDynamicSharedMemorySize, G2_SMEM_BYTES);

    __half* wfcH; cudaGetSymbolAddress((void**)&wfcH, g_wfcH);
    __half* wgtH; cudaGetSymbolAddress((void**)&wgtH, g_wgtH);
    __half* wprH; cudaGetSymbolAddress((void**)&wprH, g_wprH);

    // fused router + fc/gate weight convert (router blocks first, convert hides them)
    prepass_kernel<<<RBLKS + 2 * CBLKS_PER, 256>>>(x, wr,
                                                   (const float4*)wfc, (const float4*)wgt,
                                                   (__half2*)wfcH, (__half2*)wgtH);
    // gemm1 also converts wpr in its prologue (exact coverage: 6144*256*3 float4)
    gemm1_kernel<<<dim3(HDIM / 64, CAP / 128, EDIM), 256, G1_SMEM_BYTES>>>(
        bfc, bgt, (const float4*)wpr, (__half2*)wprH);
    gemm2_kernel<<<dim3(CDIM / 128, CAP / 128, EDIM * NSPLIT), 256, G2_SMEM_BYTES>>>(bpr);
    combine_kernel<<<NTOK, 192>>>(out);
}

// round 15
// speedup vs baseline: 1.2398x; 1.0133x over previous
#include <cuda_runtime.h>
#include <cuda_fp16.h>
#include <math.h>
#include <stdint.h>

// Problem constants
#define NTOK 2048
#define CDIM 768
#define EDIM 8
#define HDIM 3072
#define CAP  2048

// ---------------- scratch (static device memory; no allocations) ----------------
__device__ __half g_xbuf[(size_t)EDIM * CAP * CDIM];   // gathered activations (fp16)
__device__ __half g_u   [(size_t)EDIM * CAP * HDIM];   // h*silu(g) (fp16)
__device__ __half g_oh  [(size_t)3 * EDIM * CAP * CDIM]; // proj out, 3 split-K parts (fp16)
__device__ __half g_wfcH[(size_t)EDIM * CDIM * HDIM];  // fp16 weights
__device__ __half g_wgtH[(size_t)EDIM * CDIM * HDIM];
__device__ __half g_wprH[(size_t)EDIM * HDIM * CDIM];
__device__ int    g_cnt [EDIM];                        // zero at load; re-zeroed by combine
__device__ float  g_prob[EDIM * CAP];
__device__ int    g_pidx[2 * NTOK];

#define OH_STRIDE ((size_t)EDIM * CAP * CDIM)

// ---------------- helpers ----------------
__device__ __forceinline__ void mma_f16(float c[4], const unsigned a[4], const unsigned b[2]) {
    asm volatile(
        "mma.sync.aligned.m16n8k16.row.col.f32.f16.f16.f32 "
        "{%0,%1,%2,%3},{%4,%5,%6,%7},{%8,%9},{%0,%1,%2,%3};\n"
        : "+f"(c[0]), "+f"(c[1]), "+f"(c[2]), "+f"(c[3])
        : "r"(a[0]), "r"(a[1]), "r"(a[2]), "r"(a[3]), "r"(b[0]), "r"(b[1]));
}

__device__ __forceinline__ void ldsm_x4(unsigned r[4], uint32_t addr) {
    asm volatile("ldmatrix.sync.aligned.m8n8.x4.shared.b16 {%0,%1,%2,%3}, [%4];"
                 : "=r"(r[0]), "=r"(r[1]), "=r"(r[2]), "=r"(r[3]) : "r"(addr));
}
__device__ __forceinline__ void ldsm_x4t(unsigned r[4], uint32_t addr) {
    asm volatile("ldmatrix.sync.aligned.m8n8.x4.trans.shared.b16 {%0,%1,%2,%3}, [%4];"
                 : "=r"(r[0]), "=r"(r[1]), "=r"(r[2]), "=r"(r[3]) : "r"(addr));
}

__device__ __forceinline__ void cpa16(uint32_t dst, const void* src, int sz) {
    asm volatile("cp.async.cg.shared.global [%0], [%1], 16, %2;"
                 :: "r"(dst), "l"(src), "r"(sz));
}
__device__ __forceinline__ void cpa16u(uint32_t dst, const void* src) {
    asm volatile("cp.async.cg.shared.global [%0], [%1], 16;"
                 :: "r"(dst), "l"(src));
}
__device__ __forceinline__ void cpa_commit() { asm volatile("cp.async.commit_group;"); }
__device__ __forceinline__ void cpa_wait1()  { asm volatile("cp.async.wait_group 1;" ::: "memory"); }
__device__ __forceinline__ void cpa_wait0()  { asm volatile("cp.async.wait_group 0;" ::: "memory"); }

__device__ __forceinline__ uint32_t smem_u32(const void* p) {
    return (uint32_t)__cvta_generic_to_shared(p);
}

// ---------------- fused pre-pass: router blocks [0,256) + fc/gate weight-convert ----------------
#define WQUARTS (EDIM * CDIM * HDIM / 4)       // float4 per tensor: 4,718,592
#define CBLKS_PER (WQUARTS / 256)              // 18432 blocks per tensor
#define RBLKS (NTOK / 8)                       // 256 router blocks

__global__ __launch_bounds__(256) void prepass_kernel(const float* __restrict__ x,
                                                      const float* __restrict__ wr,
                                                      const float4* __restrict__ wfc,
                                                      const float4* __restrict__ wgt,
                                                      __half2* __restrict__ ofc,
                                                      __half2* __restrict__ ogt) {
    if (blockIdx.x >= RBLKS) {
        const int cb = blockIdx.x - RBLKS;
        const int which = cb / CBLKS_PER;
        const size_t i = (size_t)(cb % CBLKS_PER) * 256 + threadIdx.x;
        const float4* src = (which == 0) ? wfc : wgt;
        __half2* dst = (which == 0) ? ofc : ogt;
        float4 v = src[i];
        dst[2 * i + 0] = __floats2half2_rn(v.x, v.y);
        dst[2 * i + 1] = __floats2half2_rn(v.z, v.w);
        return;
    }

    // ---- router portion ----
    const int t = blockIdx.x * 8 + (threadIdx.x >> 5);
    const int lane = threadIdx.x & 31;
    const float* xr = x + (size_t)t * CDIM;

    float acc[EDIM];
#pragma unroll
    for (int e = 0; e < EDIM; e++) acc[e] = 0.f;
#pragma unroll
    for (int j = 0; j < CDIM / 32; j++) {
        int i = lane + 32 * j;
        float xv = xr[i];
        const float4* w4 = reinterpret_cast<const float4*>(wr + (size_t)i * EDIM);
        float4 w0 = w4[0], w1 = w4[1];
        acc[0] += xv * w0.x; acc[1] += xv * w0.y; acc[2] += xv * w0.z; acc[3] += xv * w0.w;
        acc[4] += xv * w1.x; acc[5] += xv * w1.y; acc[6] += xv * w1.z; acc[7] += xv * w1.w;
    }
#pragma unroll
    for (int off = 16; off > 0; off >>= 1) {
#pragma unroll
        for (int e = 0; e < EDIM; e++) acc[e] += __shfl_xor_sync(0xffffffffu, acc[e], off);
    }
    int e0 = 0; float l0 = acc[0];
#pragma unroll
    for (int e = 1; e < EDIM; e++) if (acc[e] > l0) { l0 = acc[e]; e0 = e; }
    int e1 = -1; float l1 = -INFINITY;
#pragma unroll
    for (int e = 0; e < EDIM; e++) if (e != e0 && acc[e] > l1) { l1 = acc[e]; e1 = e; }

    float ex = expf(l1 - l0);
    float p0 = 1.f / (1.f + ex);
    float p1 = ex * p0;

    int s0 = 0, s1 = 0;
    if (lane == 0) {
        s0 = atomicAdd(&g_cnt[e0], 1);
        s1 = atomicAdd(&g_cnt[e1], 1);
        g_prob[e0 * CAP + s0] = p0;
        g_prob[e1 * CAP + s1] = p1;
        g_pidx[2 * t + 0] = e0 * CAP + s0;
        g_pidx[2 * t + 1] = e1 * CAP + s1;
    }
    s0 = __shfl_sync(0xffffffffu, s0, 0);
    s1 = __shfl_sync(0xffffffffu, s1, 0);

    __half2* d0 = reinterpret_cast<__half2*>(g_xbuf + ((size_t)e0 * CAP + s0) * CDIM);
    __half2* d1 = reinterpret_cast<__half2*>(g_xbuf + ((size_t)e1 * CAP + s1) * CDIM);
    const float2* x2 = reinterpret_cast<const float2*>(xr);
#pragma unroll
    for (int j = 0; j < CDIM / 64; j++) {
        int i = lane + 32 * j;
        float2 v = x2[i];
        __half2 h = __floats2half2_rn(v.x, v.y);
        d0[i] = h;
        d1[i] = h;
    }
}

// ======== GEMM1: fused fc+gate, block 128x64(x2), BK=64, fp16 mma, cp.async 2-stage ========
// Grid y has one extra slice (y == MB): 48*8 = 384 dedicated converter CTAs that
// translate wpr f32 -> fp16 concurrently with the GEMM CTAs (exact coverage:
// 384 CTAs * 256 thr * 48 = 4,718,592 float4). Kernel boundary orders wprH
// before gemm2 reads it.
#define G1_AH    9216            // halves per A stage
#define G1_BH    4608            // halves per B stage (each matrix)
#define G1_BF0H  (2 * G1_AH)
#define G1_BG0H  (G1_BF0H + 2 * G1_BH)
#define G1_SMEM_BYTES ((G1_BG0H + 2 * G1_BH) * 2)
#define G1_MB    (CAP / 128)     // 16 compute m-blocks
#define CVT_CTAS (48 * 8)        // converter CTAs (x * z with y == G1_MB)
#define CVT_PER_THREAD (WQUARTS / (CVT_CTAS * 256))   // 48

__global__ __launch_bounds__(256, 2) void gemm1_kernel(const float* __restrict__ bfc,
                                                       const float* __restrict__ bgt,
                                                       const float4* __restrict__ wpr4,
                                                       __half2* __restrict__ wprH2) {
    extern __shared__ __half smh[];
    const int tid = threadIdx.x;

    // ---- converter slice (blockIdx.y == G1_MB): pure-DRAM CTAs, overlap compute ----
    if (blockIdx.y == G1_MB) {
        const size_t cid = (size_t)blockIdx.z * gridDim.x + blockIdx.x;  // 0..383
        size_t idx = cid * 256 + tid;
        const size_t stride = (size_t)CVT_CTAS * 256;
#pragma unroll 4
        for (int i = 0; i < CVT_PER_THREAD; i++, idx += stride) {
            float4 v = wpr4[idx];
            wprH2[2 * idx + 0] = __floats2half2_rn(v.x, v.y);
            wprH2[2 * idx + 1] = __floats2half2_rn(v.z, v.w);
        }
        return;
    }

    const int e   = blockIdx.z;
    const int cnt = g_cnt[e];
    const int m0  = blockIdx.y * 128;
    if (m0 >= cnt) return;
    const int n0  = blockIdx.x * 64;

    const __half* Ag = g_xbuf + (size_t)e * CAP * CDIM;
    const __half* B0 = g_wfcH + (size_t)e * CDIM * HDIM;
    const __half* B1 = g_wgtH + (size_t)e * CDIM * HDIM;

    const int lane = tid & 31, wid = tid >> 5;
    const int wm = (wid & 3) * 32, wn = (wid >> 2) * 32;
    const int gq = lane >> 2, tg = lane & 3;
    const int grp = lane >> 3, rin = lane & 7;

    const uint32_t sBase = smem_u32(smh);

    auto load_stage = [&](int buf, int k0) {
#pragma unroll
        for (int i = 0; i < 4; i++) {
            int v = tid + 256 * i, row = v >> 3, c16 = v & 7;
            int sz = (m0 + row < cnt) ? 16 : 0;
            cpa16(sBase + (uint32_t)(buf * G1_AH + row * 72 + c16 * 8) * 2,
                  Ag + (size_t)(m0 + row) * CDIM + k0 + c16 * 8, sz);
        }
#pragma unroll
        for (int i = 0; i < 2; i++) {
            int v = tid + 256 * i, row = v >> 3, c16 = v & 7;
            size_t off = (size_t)(k0 + row) * HDIM + n0 + c16 * 8;
            cpa16u(sBase + (uint32_t)(G1_BF0H + buf * G1_BH + row * 72 + c16 * 8) * 2, B0 + off);
            cpa16u(sBase + (uint32_t)(G1_BG0H + buf * G1_BH + row * 72 + c16 * 8) * 2, B1 + off);
        }
        cpa_commit();
    };

    float cf[2][4][4] = {};
    float cg[2][4][4] = {};

    const int NIT = CDIM / 64;  // 12
    load_stage(0, 0);
    load_stage(1, 64);

#pragma unroll 1
    for (int it = 0; it < NIT; ++it) {
        const int cur = it & 1;
        if (it + 1 < NIT) cpa_wait1(); else cpa_wait0();
        __syncthreads();

        const uint32_t aB  = sBase + (uint32_t)(cur * G1_AH) * 2;
        const uint32_t bfB = sBase + (uint32_t)(G1_BF0H + cur * G1_BH) * 2;
        const uint32_t bgB = sBase + (uint32_t)(G1_BG0H + cur * G1_BH) * 2;

        unsigned uA[2][2][4], uBf[2][4][2], uBg[2][4][2];

        auto ldfrag = [&](int ks, int s) {
            const int kb = ks * 16;
#pragma unroll
            for (int mt = 0; mt < 2; mt++) {
                int r = wm + mt * 16 + (grp & 1) * 8 + rin;
                ldsm_x4(uA[s][mt], aB + (uint32_t)((r * 72 + kb + (grp >> 1) * 8) * 2));
            }
#pragma unroll
            for (int p = 0; p < 2; p++) {
                int kr = kb + (grp & 1) * 8 + rin;
                int cc = wn + p * 16 + (grp >> 1) * 8;
                unsigned r4[4];
                ldsm_x4t(r4, bfB + (uint32_t)((kr * 72 + cc) * 2));
                uBf[s][2 * p + 0][0] = r4[0]; uBf[s][2 * p + 0][1] = r4[1];
                uBf[s][2 * p + 1][0] = r4[2]; uBf[s][2 * p + 1][1] = r4[3];
                ldsm_x4t(r4, bgB + (uint32_t)((kr * 72 + cc) * 2));
                uBg[s][2 * p + 0][0] = r4[0]; uBg[s][2 * p + 0][1] = r4[1];
                uBg[s][2 * p + 1][0] = r4[2]; uBg[s][2 * p + 1][1] = r4[3];
            }
        };

        ldfrag(0, 0);
#pragma unroll
        for (int ks = 0; ks < 4; ks++) {
            const int s = ks & 1;
            if (ks < 3) ldfrag(ks + 1, s ^ 1);
#pragma unroll
            for (int mt = 0; mt < 2; mt++)
#pragma unroll
                for (int nt = 0; nt < 4; nt++) {
                    mma_f16(cf[mt][nt], uA[s][mt], uBf[s][nt]);
                    mma_f16(cg[mt][nt], uA[s][mt], uBg[s][nt]);
                }
        }
        __syncthreads();
        if (it + 2 < NIT) load_stage(cur, (it + 2) * 64);
    }

    // epilogue: u = (h+bfc) * silu(g+bg) -> fp16
    __half* U = g_u + (size_t)e * CAP * HDIM;
#pragma unroll
    for (int mt = 0; mt < 2; mt++) {
#pragma unroll
        for (int nt = 0; nt < 4; nt++) {
            int col = n0 + wn + nt * 8 + tg * 2;
            float bf0 = bfc[(size_t)e * HDIM + col], bf1 = bfc[(size_t)e * HDIM + col + 1];
            float bg0 = bgt[(size_t)e * HDIM + col], bg1 = bgt[(size_t)e * HDIM + col + 1];
            int r0 = m0 + wm + mt * 16 + gq;
            if (r0 < cnt) {
                float h0 = cf[mt][nt][0] + bf0, h1 = cf[mt][nt][1] + bf1;
                float q0 = cg[mt][nt][0] + bg0, q1 = cg[mt][nt][1] + bg1;
                float u0 = h0 * (q0 / (1.f + expf(-q0)));
                float u1 = h1 * (q1 / (1.f + expf(-q1)));
                *reinterpret_cast<__half2*>(U + (size_t)r0 * HDIM + col) = __floats2half2_rn(u0, u1);
            }
            int r1 = r0 + 8;
            if (r1 < cnt) {
                float h0 = cf[mt][nt][2] + bf0, h1 = cf[mt][nt][3] + bf1;
                float q0 = cg[mt][nt][2] + bg0, q1 = cg[mt][nt][3] + bg1;
                float u0 = h0 * (q0 / (1.f + expf(-q0)));
                float u1 = h1 * (q1 / (1.f + expf(-q1)));
                *reinterpret_cast<__half2*>(U + (size_t)r1 * HDIM + col) = __floats2half2_rn(u0, u1);
            }
        }
    }
}

// ======== GEMM2: proj, block 128x128, warp 64x32, BK=64, fp16 mma, 2-stage, split-K=3 ========
#define G2_AH   9216
#define G2_BH   8704
#define G2_B0H  (2 * G2_AH)
#define G2_SMEM_BYTES ((G2_B0H + 2 * G2_BH) * 2)
#define NSPLIT 3
#define SPLITK (HDIM / NSPLIT)   // 1024

__global__ __launch_bounds__(256, 2) void gemm2_kernel(const float* __restrict__ bpr) {
    extern __shared__ __half smh[];
    const int e     = blockIdx.z / NSPLIT;
    const int split = blockIdx.z % NSPLIT;
    const int cnt   = g_cnt[e];
    const int m0    = blockIdx.y * 128;
    if (m0 >= cnt) return;
    const int n0    = blockIdx.x * 128;
    const int kbase = split * SPLITK;

    const __half* Ag = g_u + (size_t)e * CAP * HDIM + kbase;
    const __half* Bp = g_wprH + (size_t)e * HDIM * CDIM + (size_t)kbase * CDIM;

    const int tid = threadIdx.x, lane = tid & 31, wid = tid >> 5;
    const int wm = (wid & 1) * 64, wn = (wid >> 1) * 32;
    const int gq = lane >> 2, tg = lane & 3;
    const int grp = lane >> 3, rin = lane & 7;

    const uint32_t sBase = smem_u32(smh);

    auto load_stage = [&](int buf, int k0) {
#pragma unroll
        for (int i = 0; i < 4; i++) {
            int v = tid + 256 * i, row = v >> 3, c16 = v & 7;
            int sz = (m0 + row < cnt) ? 16 : 0;
            cpa16(sBase + (uint32_t)(buf * G2_AH + row * 72 + c16 * 8) * 2,
                  Ag + (size_t)(m0 + row) * HDIM + k0 + c16 * 8, sz);
        }
#pragma unroll
        for (int i = 0; i < 4; i++) {
            int v = tid + 256 * i, row = v >> 4, c16 = v & 15;
            cpa16u(sBase + (uint32_t)(G2_B0H + buf * G2_BH + row * 136 + c16 * 8) * 2,
                   Bp + (size_t)(k0 + row) * CDIM + n0 + c16 * 8);
        }
        cpa_commit();
    };

    float acc[4][4][4] = {};

    const int NIT = SPLITK / 64;  // 16
    load_stage(0, 0);
    load_stage(1, 64);

#pragma unroll 1
    for (int it = 0; it < NIT; ++it) {
        const int cur = it & 1;
        if (it + 1 < NIT) cpa_wait1(); else cpa_wait0();
        __syncthreads();

        const uint32_t aB = sBase + (uint32_t)(cur * G2_AH) * 2;
        const uint32_t bB = sBase + (uint32_t)(G2_B0H + cur * G2_BH) * 2;

        unsigned uA[2][4][4], uB[2][4][2];

        auto ldfrag = [&](int ks, int s) {
            const int kb = ks * 16;
#pragma unroll
            for (int mt = 0; mt < 4; mt++) {
                int r = wm + mt * 16 + (grp & 1) * 8 + rin;
                ldsm_x4(uA[s][mt], aB + (uint32_t)((r * 72 + kb + (grp >> 1) * 8) * 2));
            }
            {
                int kr = kb + (grp & 1) * 8 + rin;
#pragma unroll
                for (int p = 0; p < 2; p++) {
                    int cc = wn + p * 16 + (grp >> 1) * 8;
                    unsigned r4[4];
                    ldsm_x4t(r4, bB + (uint32_t)((kr * 136 + cc) * 2));
                    uB[s][2 * p + 0][0] = r4[0]; uB[s][2 * p + 0][1] = r4[1];
                    uB[s][2 * p + 1][0] = r4[2]; uB[s][2 * p + 1][1] = r4[3];
                }
            }
        };

        ldfrag(0, 0);
#pragma unroll
        for (int ks = 0; ks < 4; ks++) {
            const int s = ks & 1;
            if (ks < 3) ldfrag(ks + 1, s ^ 1);
#pragma unroll
            for (int mt = 0; mt < 4; mt++)
#pragma unroll
                for (int nt = 0; nt < 4; nt++)
                    mma_f16(acc[mt][nt], uA[s][mt], uB[s][nt]);
        }
        __syncthreads();
        if (it + 2 < NIT) load_stage(cur, (it + 2) * 64);
    }

    // fp16 partial store (split buffers summed in combine)
    __half* O = g_oh + (size_t)split * OH_STRIDE + (size_t)e * CAP * CDIM;
#pragma unroll
    for (int mt = 0; mt < 4; mt++) {
#pragma unroll
        for (int nt = 0; nt < 4; nt++) {
            int col = n0 + wn + nt * 8 + tg * 2;
            float b0 = 0.f, b1 = 0.f;
            if (split == 0) {
                b0 = bpr[(size_t)e * CDIM + col];
                b1 = bpr[(size_t)e * CDIM + col + 1];
            }
            int r0 = m0 + wm + mt * 16 + gq;
            if (r0 < cnt) {
                *reinterpret_cast<__half2*>(O + (size_t)r0 * CDIM + col) =
                    __floats2half2_rn(acc[mt][nt][0] + b0, acc[mt][nt][1] + b1);
            }
            int r1 = r0 + 8;
            if (r1 < cnt) {
                *reinterpret_cast<__half2*>(O + (size_t)r1 * CDIM + col) =
                    __floats2half2_rn(acc[mt][nt][2] + b0, acc[mt][nt][3] + b1);
            }
        }
    }
}

// ---------------- kernel 4: deterministic combine (sums 3 fp16 split parts) ----------------
// Also re-zeroes g_cnt for the next graph replay (combine is the last kernel;
// g_cnt starts zero-initialized at module load, so every launch sees zeros).
__global__ __launch_bounds__(192) void combine_kernel(float* __restrict__ out) {
    const int t = blockIdx.x;
    const int c4 = threadIdx.x;            // handles cols [4*c4, 4*c4+4)
    const int i0 = g_pidx[2 * t + 0];
    const int i1 = g_pidx[2 * t + 1];
    const float p0 = g_prob[i0];
    const float p1 = g_prob[i1];

    float s0[4] = {0.f, 0.f, 0.f, 0.f};
    float s1[4] = {0.f, 0.f, 0.f, 0.f};
#pragma unroll
    for (int sp = 0; sp < 3; sp++) {
        const __half2* A = reinterpret_cast<const __half2*>(
            g_oh + (size_t)sp * OH_STRIDE + (size_t)i0 * CDIM);
        const __half2* B = reinterpret_cast<const __half2*>(
            g_oh + (size_t)sp * OH_STRIDE + (size_t)i1 * CDIM);
        float2 a0 = __half22float2(A[2 * c4 + 0]);
        float2 a1 = __half22float2(A[2 * c4 + 1]);
        float2 b0 = __half22float2(B[2 * c4 + 0]);
        float2 b1 = __half22float2(B[2 * c4 + 1]);
        s0[0] += a0.x; s0[1] += a0.y; s0[2] += a1.x; s0[3] += a1.y;
        s1[0] += b0.x; s1[1] += b0.y; s1[2] += b1.x; s1[3] += b1.y;
    }
    float4 y;
    y.x = p0 * s0[0] + p1 * s1[0];
    y.y = p0 * s0[1] + p1 * s1[1];
    y.z = p0 * s0[2] + p1 * s1[2];
    y.w = p0 * s0[3] + p1 * s1[3];
    reinterpret_cast<float4*>(out + (size_t)t * CDIM)[c4] = y;

    // reset expert counters for the next launch (deterministic: always runs)
    if (blockIdx.x == 0 && threadIdx.x < EDIM) g_cnt[threadIdx.x] = 0;
}

// ---------------- launch ----------------
extern "C" void kernel_launch(void* const* d_in, const int* in_sizes, int n_in,
                              void* d_out, int out_size) {
    const float* x    = (const float*)d_in[0];
    const float* wr   = (const float*)d_in[1];
    const float* wfc  = (const float*)d_in[2];
    const float* bfc  = (const float*)d_in[3];
    const float* wgt  = (const float*)d_in[4];
    const float* bgt  = (const float*)d_in[5];
    const float* wpr  = (const float*)d_in[6];
    const float* bpr  = (const float*)d_in[7];
    float* out = (float*)d_out;

    // REQUIRED: dynamic smem exceeds the 48KB default opt-in
    cudaFuncSetAttribute(gemm1_kernel, cudaFuncAttributeMaxDynamicSharedMemorySize, G1_SMEM_BYTES);
    cudaFuncSetAttribute(gemm2_kernel, cudaFuncAttributeMaxDynamicSharedMemorySize, G2_SMEM_BYTES);

    __half* wfcH; cudaGetSymbolAddress((void**)&wfcH, g_wfcH);
    __half* wgtH; cudaGetSymbolAddress((void**)&wgtH, g_wgtH);
    __half* wprH; cudaGetSymbolAddress((void**)&wprH, g_wprH);

    // fused router + fc/gate weight convert (router blocks first, convert hides them)
    prepass_kernel<<<RBLKS + 2 * CBLKS_PER, 256>>>(x, wr,
                                                   (const float4*)wfc, (const float4*)wgt,
                                                   (__half2*)wfcH, (__half2*)wgtH);
    // gemm1 grid: y in [0,16) compute m-blocks, y == 16 -> wpr converter CTAs
    gemm1_kernel<<<dim3(HDIM / 64, G1_MB + 1, EDIM), 256, G1_SMEM_BYTES>>>(
        bfc, bgt, (const float4*)wpr, (__half2*)wprH);
    gemm2_kernel<<<dim3(CDIM / 128, CAP / 128, EDIM * NSPLIT), 256, G2_SMEM_BYTES>>>(bpr);
    combine_kernel<<<NTOK, 192>>>(out);
}

// round 16
// speedup vs baseline: 1.2894x; 1.0400x over previous
#include <cuda_runtime.h>
#include <cuda_fp16.h>
#include <math.h>
#include <stdint.h>

// Problem constants
#define NTOK 2048
#define CDIM 768
#define EDIM 8
#define HDIM 3072
#define CAP  2048

// ---------------- scratch (static device memory; no allocations) ----------------
__device__ __half g_xbuf[(size_t)EDIM * CAP * CDIM];   // gathered activations (fp16)
__device__ __half g_u   [(size_t)EDIM * CAP * HDIM];   // h*silu(g) (fp16)
__device__ __half g_oh  [(size_t)3 * EDIM * CAP * CDIM]; // proj out, 3 split-K parts (fp16)
__device__ __half g_wfcH[(size_t)EDIM * CDIM * HDIM];  // fp16 weights
__device__ __half g_wgtH[(size_t)EDIM * CDIM * HDIM];
__device__ __half g_wprH[(size_t)EDIM * HDIM * CDIM];
__device__ int    g_cnt [EDIM];                        // zero at load; re-zeroed by combine
__device__ float  g_prob[EDIM * CAP];
__device__ int    g_pidx[2 * NTOK];

#define OH_STRIDE ((size_t)EDIM * CAP * CDIM)

// ---------------- helpers ----------------
__device__ __forceinline__ void mma_f16(float c[4], const unsigned a[4], const unsigned b[2]) {
    asm volatile(
        "mma.sync.aligned.m16n8k16.row.col.f32.f16.f16.f32 "
        "{%0,%1,%2,%3},{%4,%5,%6,%7},{%8,%9},{%0,%1,%2,%3};\n"
        : "+f"(c[0]), "+f"(c[1]), "+f"(c[2]), "+f"(c[3])
        : "r"(a[0]), "r"(a[1]), "r"(a[2]), "r"(a[3]), "r"(b[0]), "r"(b[1]));
}

__device__ __forceinline__ void ldsm_x4(unsigned r[4], uint32_t addr) {
    asm volatile("ldmatrix.sync.aligned.m8n8.x4.shared.b16 {%0,%1,%2,%3}, [%4];"
                 : "=r"(r[0]), "=r"(r[1]), "=r"(r[2]), "=r"(r[3]) : "r"(addr));
}
__device__ __forceinline__ void ldsm_x4t(unsigned r[4], uint32_t addr) {
    asm volatile("ldmatrix.sync.aligned.m8n8.x4.trans.shared.b16 {%0,%1,%2,%3}, [%4];"
                 : "=r"(r[0]), "=r"(r[1]), "=r"(r[2]), "=r"(r[3]) : "r"(addr));
}

__device__ __forceinline__ void cpa16(uint32_t dst, const void* src, int sz) {
    asm volatile("cp.async.cg.shared.global [%0], [%1], 16, %2;"
                 :: "r"(dst), "l"(src), "r"(sz));
}
__device__ __forceinline__ void cpa16u(uint32_t dst, const void* src) {
    asm volatile("cp.async.cg.shared.global [%0], [%1], 16;"
                 :: "r"(dst), "l"(src));
}
__device__ __forceinline__ void cpa_commit() { asm volatile("cp.async.commit_group;"); }
__device__ __forceinline__ void cpa_wait1()  { asm volatile("cp.async.wait_group 1;" ::: "memory"); }
__device__ __forceinline__ void cpa_wait0()  { asm volatile("cp.async.wait_group 0;" ::: "memory"); }

__device__ __forceinline__ uint32_t smem_u32(const void* p) {
    return (uint32_t)__cvta_generic_to_shared(p);
}

__device__ __forceinline__ unsigned pack_h2(float a, float b) {
    __half2 h = __floats2half2_rn(a, b);
    return *reinterpret_cast<unsigned*>(&h);
}

// convert two consecutive float4 (8 floats) -> one uint4 of 8 halves
__device__ __forceinline__ uint4 cvt8(float4 v0, float4 v1) {
    uint4 o;
    o.x = pack_h2(v0.x, v0.y);
    o.y = pack_h2(v0.z, v0.w);
    o.z = pack_h2(v1.x, v1.y);
    o.w = pack_h2(v1.z, v1.w);
    return o;
}

// ---------------- fused pre-pass: router blocks [0,256) + fc/gate weight-convert ----------------
#define WQUARTS (EDIM * CDIM * HDIM / 4)       // float4 per tensor: 4,718,592
#define WPAIRS  (WQUARTS / 2)                  // float4-pairs per tensor: 2,359,296
#define PBLKS_PER (WPAIRS / 256)               // 9216 convert blocks per tensor
#define RBLKS (NTOK / 8)                       // 256 router blocks

__global__ __launch_bounds__(256) void prepass_kernel(const float* __restrict__ x,
                                                      const float* __restrict__ wr,
                                                      const float4* __restrict__ wfc,
                                                      const float4* __restrict__ wgt,
                                                      uint4* __restrict__ ofc,
                                                      uint4* __restrict__ ogt) {
    if (blockIdx.x >= RBLKS) {
        // ---- convert portion: one packed 16B store per thread ----
        const int cb = blockIdx.x - RBLKS;
        const int which = cb / PBLKS_PER;
        const size_t p = (size_t)(cb % PBLKS_PER) * 256 + threadIdx.x;  // pair index
        const float4* src = (which == 0) ? wfc : wgt;
        uint4* dst = (which == 0) ? ofc : ogt;
        float4 v0 = src[2 * p];
        float4 v1 = src[2 * p + 1];
        dst[p] = cvt8(v0, v1);
        return;
    }

    // ---- router portion ----
    const int t = blockIdx.x * 8 + (threadIdx.x >> 5);
    const int lane = threadIdx.x & 31;
    const float* xr = x + (size_t)t * CDIM;

    float acc[EDIM];
#pragma unroll
    for (int e = 0; e < EDIM; e++) acc[e] = 0.f;
#pragma unroll
    for (int j = 0; j < CDIM / 32; j++) {
        int i = lane + 32 * j;
        float xv = xr[i];
        const float4* w4 = reinterpret_cast<const float4*>(wr + (size_t)i * EDIM);
        float4 w0 = w4[0], w1 = w4[1];
        acc[0] += xv * w0.x; acc[1] += xv * w0.y; acc[2] += xv * w0.z; acc[3] += xv * w0.w;
        acc[4] += xv * w1.x; acc[5] += xv * w1.y; acc[6] += xv * w1.z; acc[7] += xv * w1.w;
    }
#pragma unroll
    for (int off = 16; off > 0; off >>= 1) {
#pragma unroll
        for (int e = 0; e < EDIM; e++) acc[e] += __shfl_xor_sync(0xffffffffu, acc[e], off);
    }
    int e0 = 0; float l0 = acc[0];
#pragma unroll
    for (int e = 1; e < EDIM; e++) if (acc[e] > l0) { l0 = acc[e]; e0 = e; }
    int e1 = -1; float l1 = -INFINITY;
#pragma unroll
    for (int e = 0; e < EDIM; e++) if (e != e0 && acc[e] > l1) { l1 = acc[e]; e1 = e; }

    float ex = expf(l1 - l0);
    float p0 = 1.f / (1.f + ex);
    float p1 = ex * p0;

    int s0 = 0, s1 = 0;
    if (lane == 0) {
        s0 = atomicAdd(&g_cnt[e0], 1);
        s1 = atomicAdd(&g_cnt[e1], 1);
        g_prob[e0 * CAP + s0] = p0;
        g_prob[e1 * CAP + s1] = p1;
        g_pidx[2 * t + 0] = e0 * CAP + s0;
        g_pidx[2 * t + 1] = e1 * CAP + s1;
    }
    s0 = __shfl_sync(0xffffffffu, s0, 0);
    s1 = __shfl_sync(0xffffffffu, s1, 0);

    __half2* d0 = reinterpret_cast<__half2*>(g_xbuf + ((size_t)e0 * CAP + s0) * CDIM);
    __half2* d1 = reinterpret_cast<__half2*>(g_xbuf + ((size_t)e1 * CAP + s1) * CDIM);
    const float2* x2 = reinterpret_cast<const float2*>(xr);
#pragma unroll
    for (int j = 0; j < CDIM / 64; j++) {
        int i = lane + 32 * j;
        float2 v = x2[i];
        __half2 h = __floats2half2_rn(v.x, v.y);
        d0[i] = h;
        d1[i] = h;
    }
}

// ======== GEMM1: fused fc+gate, block 128x64(x2), BK=64, fp16 mma, cp.async 2-stage ========
// Grid y has one extra slice (y == MB): 384 converter CTAs translate wpr f32 -> fp16
// concurrently with the GEMM CTAs (24 pairs/thread, 16B packed stores; exact coverage:
// 384 * 256 * 24 pairs = 2,359,296 = WPAIRS). Kernel boundary orders wprH before gemm2.
#define G1_AH    9216            // halves per A stage
#define G1_BH    4608            // halves per B stage (each matrix)
#define G1_BF0H  (2 * G1_AH)
#define G1_BG0H  (G1_BF0H + 2 * G1_BH)
#define G1_SMEM_BYTES ((G1_BG0H + 2 * G1_BH) * 2)
#define G1_MB    (CAP / 128)     // 16 compute m-blocks
#define CVT_CTAS (48 * 8)        // converter CTAs (x * z with y == G1_MB)
#define CVT_PAIRS_PER_THREAD (WPAIRS / (CVT_CTAS * 256))   // 24

__global__ __launch_bounds__(256, 2) void gemm1_kernel(const float* __restrict__ bfc,
                                                       const float* __restrict__ bgt,
                                                       const float4* __restrict__ wpr4,
                                                       uint4* __restrict__ wprH4) {
    extern __shared__ __half smh[];
    const int tid = threadIdx.x;

    // ---- converter slice (blockIdx.y == G1_MB): pure-DRAM CTAs, overlap compute ----
    if (blockIdx.y == G1_MB) {
        const size_t cid = (size_t)blockIdx.z * gridDim.x + blockIdx.x;  // 0..383
        size_t p = cid * 256 + tid;
        const size_t stride = (size_t)CVT_CTAS * 256;
#pragma unroll 4
        for (int i = 0; i < CVT_PAIRS_PER_THREAD; i++, p += stride) {
            float4 v0 = wpr4[2 * p];
            float4 v1 = wpr4[2 * p + 1];
            wprH4[p] = cvt8(v0, v1);
        }
        return;
    }

    const int e   = blockIdx.z;
    const int cnt = g_cnt[e];
    const int m0  = blockIdx.y * 128;
    if (m0 >= cnt) return;
    const int n0  = blockIdx.x * 64;

    const __half* Ag = g_xbuf + (size_t)e * CAP * CDIM;
    const __half* B0 = g_wfcH + (size_t)e * CDIM * HDIM;
    const __half* B1 = g_wgtH + (size_t)e * CDIM * HDIM;

    const int lane = tid & 31, wid = tid >> 5;
    const int wm = (wid & 3) * 32, wn = (wid >> 2) * 32;
    const int gq = lane >> 2, tg = lane & 3;
    const int grp = lane >> 3, rin = lane & 7;

    const uint32_t sBase = smem_u32(smh);

    auto load_stage = [&](int buf, int k0) {
#pragma unroll
        for (int i = 0; i < 4; i++) {
            int v = tid + 256 * i, row = v >> 3, c16 = v & 7;
            int sz = (m0 + row < cnt) ? 16 : 0;
            cpa16(sBase + (uint32_t)(buf * G1_AH + row * 72 + c16 * 8) * 2,
                  Ag + (size_t)(m0 + row) * CDIM + k0 + c16 * 8, sz);
        }
#pragma unroll
        for (int i = 0; i < 2; i++) {
            int v = tid + 256 * i, row = v >> 3, c16 = v & 7;
            size_t off = (size_t)(k0 + row) * HDIM + n0 + c16 * 8;
            cpa16u(sBase + (uint32_t)(G1_BF0H + buf * G1_BH + row * 72 + c16 * 8) * 2, B0 + off);
            cpa16u(sBase + (uint32_t)(G1_BG0H + buf * G1_BH + row * 72 + c16 * 8) * 2, B1 + off);
        }
        cpa_commit();
    };

    float cf[2][4][4] = {};
    float cg[2][4][4] = {};

    const int NIT = CDIM / 64;  // 12
    load_stage(0, 0);
    load_stage(1, 64);

#pragma unroll 1
    for (int it = 0; it < NIT; ++it) {
        const int cur = it & 1;
        if (it + 1 < NIT) cpa_wait1(); else cpa_wait0();
        __syncthreads();

        const uint32_t aB  = sBase + (uint32_t)(cur * G1_AH) * 2;
        const uint32_t bfB = sBase + (uint32_t)(G1_BF0H + cur * G1_BH) * 2;
        const uint32_t bgB = sBase + (uint32_t)(G1_BG0H + cur * G1_BH) * 2;

        unsigned uA[2][2][4], uBf[2][4][2], uBg[2][4][2];

        auto ldfrag = [&](int ks, int s) {
            const int kb = ks * 16;
#pragma unroll
            for (int mt = 0; mt < 2; mt++) {
                int r = wm + mt * 16 + (grp & 1) * 8 + rin;
                ldsm_x4(uA[s][mt], aB + (uint32_t)((r * 72 + kb + (grp >> 1) * 8) * 2));
            }
#pragma unroll
            for (int p = 0; p < 2; p++) {
                int kr = kb + (grp & 1) * 8 + rin;
                int cc = wn + p * 16 + (grp >> 1) * 8;
                unsigned r4[4];
                ldsm_x4t(r4, bfB + (uint32_t)((kr * 72 + cc) * 2));
                uBf[s][2 * p + 0][0] = r4[0]; uBf[s][2 * p + 0][1] = r4[1];
                uBf[s][2 * p + 1][0] = r4[2]; uBf[s][2 * p + 1][1] = r4[3];
                ldsm_x4t(r4, bgB + (uint32_t)((kr * 72 + cc) * 2));
                uBg[s][2 * p + 0][0] = r4[0]; uBg[s][2 * p + 0][1] = r4[1];
                uBg[s][2 * p + 1][0] = r4[2]; uBg[s][2 * p + 1][1] = r4[3];
            }
        };

        ldfrag(0, 0);
#pragma unroll
        for (int ks = 0; ks < 4; ks++) {
            const int s = ks & 1;
            if (ks < 3) ldfrag(ks + 1, s ^ 1);
#pragma unroll
            for (int mt = 0; mt < 2; mt++)
#pragma unroll
                for (int nt = 0; nt < 4; nt++) {
                    mma_f16(cf[mt][nt], uA[s][mt], uBf[s][nt]);
                    mma_f16(cg[mt][nt], uA[s][mt], uBg[s][nt]);
                }
        }
        __syncthreads();
        if (it + 2 < NIT) load_stage(cur, (it + 2) * 64);
    }

    // epilogue: u = (h+bfc) * silu(g+bg) -> fp16
    __half* U = g_u + (size_t)e * CAP * HDIM;
#pragma unroll
    for (int mt = 0; mt < 2; mt++) {
#pragma unroll
        for (int nt = 0; nt < 4; nt++) {
            int col = n0 + wn + nt * 8 + tg * 2;
            float bf0 = bfc[(size_t)e * HDIM + col], bf1 = bfc[(size_t)e * HDIM + col + 1];
            float bg0 = bgt[(size_t)e * HDIM + col], bg1 = bgt[(size_t)e * HDIM + col + 1];
            int r0 = m0 + wm + mt * 16 + gq;
            if (r0 < cnt) {
                float h0 = cf[mt][nt][0] + bf0, h1 = cf[mt][nt][1] + bf1;
                float q0 = cg[mt][nt][0] + bg0, q1 = cg[mt][nt][1] + bg1;
                float u0 = h0 * (q0 / (1.f + expf(-q0)));
                float u1 = h1 * (q1 / (1.f + expf(-q1)));
                *reinterpret_cast<__half2*>(U + (size_t)r0 * HDIM + col) = __floats2half2_rn(u0, u1);
            }
            int r1 = r0 + 8;
            if (r1 < cnt) {
                float h0 = cf[mt][nt][2] + bf0, h1 = cf[mt][nt][3] + bf1;
                float q0 = cg[mt][nt][2] + bg0, q1 = cg[mt][nt][3] + bg1;
                float u0 = h0 * (q0 / (1.f + expf(-q0)));
                float u1 = h1 * (q1 / (1.f + expf(-q1)));
                *reinterpret_cast<__half2*>(U + (size_t)r1 * HDIM + col) = __floats2half2_rn(u0, u1);
            }
        }
    }
}

// ======== GEMM2: proj, block 128x128, warp 64x32, BK=64, fp16 mma, 2-stage, split-K=3 ========
#define G2_AH   9216
#define G2_BH   8704
#define G2_B0H  (2 * G2_AH)
#define G2_SMEM_BYTES ((G2_B0H + 2 * G2_BH) * 2)
#define NSPLIT 3
#define SPLITK (HDIM / NSPLIT)   // 1024

__global__ __launch_bounds__(256, 2) void gemm2_kernel(const float* __restrict__ bpr) {
    extern __shared__ __half smh[];
    const int e     = blockIdx.z / NSPLIT;
    const int split = blockIdx.z % NSPLIT;
    const int cnt   = g_cnt[e];
    const int m0    = blockIdx.y * 128;
    if (m0 >= cnt) return;
    const int n0    = blockIdx.x * 128;
    const int kbase = split * SPLITK;

    const __half* Ag = g_u + (size_t)e * CAP * HDIM + kbase;
    const __half* Bp = g_wprH + (size_t)e * HDIM * CDIM + (size_t)kbase * CDIM;

    const int tid = threadIdx.x, lane = tid & 31, wid = tid >> 5;
    const int wm = (wid & 1) * 64, wn = (wid >> 1) * 32;
    const int gq = lane >> 2, tg = lane & 3;
    const int grp = lane >> 3, rin = lane & 7;

    const uint32_t sBase = smem_u32(smh);

    auto load_stage = [&](int buf, int k0) {
#pragma unroll
        for (int i = 0; i < 4; i++) {
            int v = tid + 256 * i, row = v >> 3, c16 = v & 7;
            int sz = (m0 + row < cnt) ? 16 : 0;
            cpa16(sBase + (uint32_t)(buf * G2_AH + row * 72 + c16 * 8) * 2,
                  Ag + (size_t)(m0 + row) * HDIM + k0 + c16 * 8, sz);
        }
#pragma unroll
        for (int i = 0; i < 4; i++) {
            int v = tid + 256 * i, row = v >> 4, c16 = v & 15;
            cpa16u(sBase + (uint32_t)(G2_B0H + buf * G2_BH + row * 136 + c16 * 8) * 2,
                   Bp + (size_t)(k0 + row) * CDIM + n0 + c16 * 8);
        }
        cpa_commit();
    };

    float acc[4][4][4] = {};

    const int NIT = SPLITK / 64;  // 16
    load_stage(0, 0);
    load_stage(1, 64);

#pragma unroll 1
    for (int it = 0; it < NIT; ++it) {
        const int cur = it & 1;
        if (it + 1 < NIT) cpa_wait1(); else cpa_wait0();
        __syncthreads();

        const uint32_t aB = sBase + (uint32_t)(cur * G2_AH) * 2;
        const uint32_t bB = sBase + (uint32_t)(G2_B0H + cur * G2_BH) * 2;

        unsigned uA[2][4][4], uB[2][4][2];

        auto ldfrag = [&](int ks, int s) {
            const int kb = ks * 16;
#pragma unroll
            for (int mt = 0; mt < 4; mt++) {
                int r = wm + mt * 16 + (grp & 1) * 8 + rin;
                ldsm_x4(uA[s][mt], aB + (uint32_t)((r * 72 + kb + (grp >> 1) * 8) * 2));
            }
            {
                int kr = kb + (grp & 1) * 8 + rin;
#pragma unroll
                for (int p = 0; p < 2; p++) {
                    int cc = wn + p * 16 + (grp >> 1) * 8;
                    unsigned r4[4];
                    ldsm_x4t(r4, bB + (uint32_t)((kr * 136 + cc) * 2));
                    uB[s][2 * p + 0][0] = r4[0]; uB[s][2 * p + 0][1] = r4[1];
                    uB[s][2 * p + 1][0] = r4[2]; uB[s][2 * p + 1][1] = r4[3];
                }
            }
        };

        ldfrag(0, 0);
#pragma unroll
        for (int ks = 0; ks < 4; ks++) {
            const int s = ks & 1;
            if (ks < 3) ldfrag(ks + 1, s ^ 1);
#pragma unroll
            for (int mt = 0; mt < 4; mt++)
#pragma unroll
                for (int nt = 0; nt < 4; nt++)
                    mma_f16(acc[mt][nt], uA[s][mt], uB[s][nt]);
        }
        __syncthreads();
        if (it + 2 < NIT) load_stage(cur, (it + 2) * 64);
    }

    // fp16 partial store (split buffers summed in combine)
    __half* O = g_oh + (size_t)split * OH_STRIDE + (size_t)e * CAP * CDIM;
#pragma unroll
    for (int mt = 0; mt < 4; mt++) {
#pragma unroll
        for (int nt = 0; nt < 4; nt++) {
            int col = n0 + wn + nt * 8 + tg * 2;
            float b0 = 0.f, b1 = 0.f;
            if (split == 0) {
                b0 = bpr[(size_t)e * CDIM + col];
                b1 = bpr[(size_t)e * CDIM + col + 1];
            }
            int r0 = m0 + wm + mt * 16 + gq;
            if (r0 < cnt) {
                *reinterpret_cast<__half2*>(O + (size_t)r0 * CDIM + col) =
                    __floats2half2_rn(acc[mt][nt][0] + b0, acc[mt][nt][1] + b1);
            }
            int r1 = r0 + 8;
            if (r1 < cnt) {
                *reinterpret_cast<__half2*>(O + (size_t)r1 * CDIM + col) =
                    __floats2half2_rn(acc[mt][nt][2] + b0, acc[mt][nt][3] + b1);
            }
        }
    }
}

// ---------------- kernel 4: combine, 4 tokens per block (latency-optimized) ----------------
// Also re-zeroes g_cnt for the next graph replay.
#define CMB_TOK 4
__global__ __launch_bounds__(192) void combine_kernel(float* __restrict__ out) {
    const int tbase = blockIdx.x * CMB_TOK;
    const int c4 = threadIdx.x;            // cols [4*c4, 4*c4+4)

    int   i0[CMB_TOK], i1[CMB_TOK];
    float p0[CMB_TOK], p1[CMB_TOK];
#pragma unroll
    for (int k = 0; k < CMB_TOK; k++) {
        i0[k] = g_pidx[2 * (tbase + k) + 0];
        i1[k] = g_pidx[2 * (tbase + k) + 1];
    }
#pragma unroll
    for (int k = 0; k < CMB_TOK; k++) {
        p0[k] = g_prob[i0[k]];
        p1[k] = g_prob[i1[k]];
    }

    float s0[CMB_TOK][4], s1[CMB_TOK][4];
#pragma unroll
    for (int k = 0; k < CMB_TOK; k++)
#pragma unroll
        for (int j = 0; j < 4; j++) { s0[k][j] = 0.f; s1[k][j] = 0.f; }

#pragma unroll
    for (int sp = 0; sp < 3; sp++) {
        // issue all 8 independent 8B loads for this split before consuming
        float2 a0[CMB_TOK], a1[CMB_TOK], b0[CMB_TOK], b1[CMB_TOK];
#pragma unroll
        for (int k = 0; k < CMB_TOK; k++) {
            const __half2* A = reinterpret_cast<const __half2*>(
                g_oh + (size_t)sp * OH_STRIDE + (size_t)i0[k] * CDIM);
            const __half2* B = reinterpret_cast<const __half2*>(
                g_oh + (size_t)sp * OH_STRIDE + (size_t)i1[k] * CDIM);
            a0[k] = __half22float2(A[2 * c4 + 0]);
            a1[k] = __half22float2(A[2 * c4 + 1]);
            b0[k] = __half22float2(B[2 * c4 + 0]);
            b1[k] = __half22float2(B[2 * c4 + 1]);
        }
#pragma unroll
        for (int k = 0; k < CMB_TOK; k++) {
            s0[k][0] += a0[k].x; s0[k][1] += a0[k].y; s0[k][2] += a1[k].x; s0[k][3] += a1[k].y;
            s1[k][0] += b0[k].x; s1[k][1] += b0[k].y; s1[k][2] += b1[k].x; s1[k][3] += b1[k].y;
        }
    }

#pragma unroll
    for (int k = 0; k < CMB_TOK; k++) {
        float4 y;
        y.x = p0[k] * s0[k][0] + p1[k] * s1[k][0];
        y.y = p0[k] * s0[k][1] + p1[k] * s1[k][1];
        y.z = p0[k] * s0[k][2] + p1[k] * s1[k][2];
        y.w = p0[k] * s0[k][3] + p1[k] * s1[k][3];
        reinterpret_cast<float4*>(out + (size_t)(tbase + k) * CDIM)[c4] = y;
    }

    // reset expert counters for the next launch (deterministic: always runs)
    if (blockIdx.x == 0 && threadIdx.x < EDIM) g_cnt[threadIdx.x] = 0;
}

// ---------------- launch ----------------
extern "C" void kernel_launch(void* const* d_in, const int* in_sizes, int n_in,
                              void* d_out, int out_size) {
    const float* x    = (const float*)d_in[0];
    const float* wr   = (const float*)d_in[1];
    const float* wfc  = (const float*)d_in[2];
    const float* bfc  = (const float*)d_in[3];
    const float* wgt  = (const float*)d_in[4];
    const float* bgt  = (const float*)d_in[5];
    const float* wpr  = (const float*)d_in[6];
    const float* bpr  = (const float*)d_in[7];
    float* out = (float*)d_out;

    // REQUIRED: dynamic smem exceeds the 48KB default opt-in
    cudaFuncSetAttribute(gemm1_kernel, cudaFuncAttributeMaxDynamicSharedMemorySize, G1_SMEM_BYTES);
    cudaFuncSetAttribute(gemm2_kernel, cudaFuncAttributeMaxDynamicSharedMemorySize, G2_SMEM_BYTES);

    __half* wfcH; cudaGetSymbolAddress((void**)&wfcH, g_wfcH);
    __half* wgtH; cudaGetSymbolAddress((void**)&wgtH, g_wgtH);
    __half* wprH; cudaGetSymbolAddress((void**)&wprH, g_wprH);

    // fused router + fc/gate weight convert (packed 16B stores)
    prepass_kernel<<<RBLKS + 2 * PBLKS_PER, 256>>>(x, wr,
                                                   (const float4*)wfc, (const float4*)wgt,
                                                   (uint4*)wfcH, (uint4*)wgtH);
    // gemm1 grid: y in [0,16) compute m-blocks, y == 16 -> wpr converter CTAs
    gemm1_kernel<<<dim3(HDIM / 64, G1_MB + 1, EDIM), 256, G1_SMEM_BYTES>>>(
        bfc, bgt, (const float4*)wpr, (uint4*)wprH);
    gemm2_kernel<<<dim3(CDIM / 128, CAP / 128, EDIM * NSPLIT), 256, G2_SMEM_BYTES>>>(bpr);
    combine_kernel<<<NTOK / CMB_TOK, 192>>>(out);
}